// round 5
// baseline (speedup 1.0000x reference)
#include <cuda_runtime.h>
#include <cuda_fp16.h>

#define NN 100000
#define NE 1600000

// ---------------- device scratch ----------------
__device__ int g_srt[NE];
__device__ unsigned char g_sign[NE];
__device__ int g_cnt3[3 * NN + 1];   // [0,NN)=indeg  [NN,2NN)=outdeg  [2NN,3NN)=cntpos  [3NN]=ctr
__device__ int g_rowbeg[NN];
__device__ int g_wptr[NN];
__device__ float g_normsq[NN];
__device__ float g_h1[NN * 64];
__device__ float g_h2[NN * 16];
__device__ uint4 g_h1b[NN * 8];          // fp16 h1, 128B/row
__device__ unsigned int g_h2b[NN * 8];   // fp16 h2, 32B/row (half2 x8)
__device__ unsigned int g_u1p[NN * 32];  // 64 half per node
__device__ unsigned int g_u1n[NN * 32];
__device__ unsigned int g_u2p[NN * 8];   // 16 half per node
__device__ unsigned int g_u2n[NN * 8];

#define g_indeg  (g_cnt3)
#define g_outdeg (g_cnt3 + NN)
#define g_cntpos (g_cnt3 + 2 * NN)

// ---------------- zero ----------------
__global__ void k_zero() {
    int i = blockIdx.x * blockDim.x + threadIdx.x;
    if (i < 3 * NN + 1) g_cnt3[i] = 0;
}

// ---------------- degrees ----------------
__global__ void k_prep(const int* __restrict__ ei) {
    int e = blockIdx.x * blockDim.x + threadIdx.x;
    if (e >= NE) return;
    atomicAdd(&g_outdeg[ei[e]], 1);
    atomicAdd(&g_indeg[ei[NE + e]], 1);
}

// ---------------- CSR offsets via block-aggregated atomic ----------------
__global__ void k_alloc() {
    __shared__ int warpsum[8];
    __shared__ int sbase;
    int i = blockIdx.x * 256 + threadIdx.x;
    int v = (i < NN) ? g_indeg[i] : 0;
    int lane = threadIdx.x & 31, w = threadIdx.x >> 5;
    int incl = v;
#pragma unroll
    for (int o = 1; o < 32; o <<= 1) {
        int u = __shfl_up_sync(0xffffffffu, incl, o);
        if (lane >= o) incl += u;
    }
    if (lane == 31) warpsum[w] = incl;
    __syncthreads();
    if (w == 0) {
        int s = (lane < 8) ? warpsum[lane] : 0;
#pragma unroll
        for (int o = 1; o < 8; o <<= 1) {
            int u = __shfl_up_sync(0xffffffffu, s, o);
            if (lane >= o) s += u;
        }
        if (lane < 8) warpsum[lane] = s;
        if (lane == 7) sbase = atomicAdd(&g_cnt3[3 * NN], s);
    }
    __syncthreads();
    int excl = incl - v + (w ? warpsum[w - 1] : 0);
    if (i < NN) {
        int r = sbase + excl;
        g_rowbeg[i] = r;
        g_wptr[i] = r;
    }
}

__global__ void k_scatter(const int* __restrict__ ei) {
    int e = blockIdx.x * blockDim.x + threadIdx.x;
    if (e >= NE) return;
    int s = ei[e];
    int d = ei[NE + e];
    int pos = atomicAdd(&g_wptr[d], 1);
    g_srt[pos] = s;
}

// ---------------- GEMM: h1 = x @ W1^T ; 128 rows x 64 cols per block ----------------
// thread = 4 rows x 8 cols  (6 LDS : 32 FFMA per k)
__global__ void __launch_bounds__(256) k_gemm64(const float* __restrict__ x, const float* __restrict__ W) {
    __shared__ float Ws[64 * 64];       // Ws[k*64+c] = W[c*64+k]
    __shared__ float sx[128 * 68];      // 128 rows, stride 68
    int t = threadIdx.x;
    for (int i = t; i < 4096; i += 256) {
        int c = i >> 6, k = i & 63;
        Ws[k * 64 + c] = W[i];
    }
    int r0 = blockIdx.x * 128;
    int nrows = NN - r0; if (nrows > 128) nrows = 128;
    for (int i = t; i < nrows * 16; i += 256) {
        int row = i >> 4, cc = i & 15;
        float4 v = ((const float4*)x)[(r0 + row) * 16 + cc];
        *(float4*)&sx[row * 68 + cc * 4] = v;
    }
    __syncthreads();
    int tc = t & 7;      // col octet: cols tc*8 .. +7
    int tr = t >> 3;     // row quad: rows tr*4 .. +3
    int rbase = tr * 4;
    float a[4][8];
#pragma unroll
    for (int r = 0; r < 4; r++)
#pragma unroll
        for (int c = 0; c < 8; c++) a[r][c] = 0.f;
#pragma unroll 4
    for (int k = 0; k < 64; k++) {
        float4 w0 = *(const float4*)&Ws[k * 64 + tc * 8];
        float4 w1 = *(const float4*)&Ws[k * 64 + tc * 8 + 4];
        float xv[4];
#pragma unroll
        for (int r = 0; r < 4; r++) xv[r] = sx[(rbase + r) * 68 + k];
#pragma unroll
        for (int r = 0; r < 4; r++) {
            a[r][0] += xv[r] * w0.x; a[r][1] += xv[r] * w0.y;
            a[r][2] += xv[r] * w0.z; a[r][3] += xv[r] * w0.w;
            a[r][4] += xv[r] * w1.x; a[r][5] += xv[r] * w1.y;
            a[r][6] += xv[r] * w1.z; a[r][7] += xv[r] * w1.w;
        }
    }
#pragma unroll
    for (int r = 0; r < 4; r++) {
        int row = r0 + rbase + r;
        if (rbase + r < nrows) {
            float4 o0 = {a[r][0], a[r][1], a[r][2], a[r][3]};
            float4 o1 = {a[r][4], a[r][5], a[r][6], a[r][7]};
            ((float4*)g_h1)[row * 16 + tc * 2]     = o0;
            ((float4*)g_h1)[row * 16 + tc * 2 + 1] = o1;
            uint4 hb;
            ((half2*)&hb)[0] = __floats2half2_rn(a[r][0], a[r][1]);
            ((half2*)&hb)[1] = __floats2half2_rn(a[r][2], a[r][3]);
            ((half2*)&hb)[2] = __floats2half2_rn(a[r][4], a[r][5]);
            ((half2*)&hb)[3] = __floats2half2_rn(a[r][6], a[r][7]);
            g_h1b[row * 8 + tc] = hb;
        }
    }
}

// ---------------- E1 layer1: signs + pos counts (fp16 gathers) ----------------
__global__ void k_e1_64() {
    int wid = (blockIdx.x * blockDim.x + threadIdx.x) >> 5;
    if (wid >= NN) return;
    int lane = threadIdx.x & 31;
    int g = lane >> 3, l8 = lane & 7;
    const float4* h1v = (const float4*)g_h1;
    float4 d0 = h1v[wid * 16 + l8 * 2];
    float4 d1 = h1v[wid * 16 + l8 * 2 + 1];
    float nq = d0.x * d0.x + d0.y * d0.y + d0.z * d0.z + d0.w * d0.w
             + d1.x * d1.x + d1.y * d1.y + d1.z * d1.z + d1.w * d1.w;
#pragma unroll
    for (int o = 4; o; o >>= 1) nq += __shfl_xor_sync(0xffffffffu, nq, o);
    if (lane == 0) g_normsq[wid] = nq;
    int beg = g_rowbeg[wid], cnt = g_indeg[wid];
    unsigned gm = 0xFFu << (g * 8);
    for (int i = g; i < cnt; i += 4) {
        int idx = beg + i;
        int s = g_srt[idx];
        uint4 sv = g_h1b[s * 8 + l8];
        float2 f0 = __half22float2(((half2*)&sv)[0]);
        float2 f1 = __half22float2(((half2*)&sv)[1]);
        float2 f2 = __half22float2(((half2*)&sv)[2]);
        float2 f3 = __half22float2(((half2*)&sv)[3]);
        float a = d0.x * f0.x + d0.y * f0.y + d0.z * f1.x + d0.w * f1.y
                + d1.x * f2.x + d1.y * f2.y + d1.z * f3.x + d1.w * f3.y;
        a += __shfl_xor_sync(gm, a, 1);
        a += __shfl_xor_sync(gm, a, 2);
        a += __shfl_xor_sync(gm, a, 4);
        if (l8 == 0) {
            bool sg = a > 0.f;
            g_sign[idx] = (unsigned char)sg;
            if (sg) atomicAdd(&g_cntpos[s], 1);
        }
    }
}

// ---------------- U1: weights + fp16 message tables (layer 1) ----------------
__global__ void k_u1() {
    int gid = blockIdx.x * blockDim.x + threadIdx.x;
    if (gid >= NN * 16) return;
    int n = gid >> 4, q = gid & 15;
    bool sp = g_normsq[n] > 0.f;
    int p = g_cntpos[n] + (sp ? 1 : 0);
    int tot = g_outdeg[n] + 1;
    const float E1c = 2.718281828459045f;
    const float EIc = 0.36787944117144233f;
    float denom = (float)p * E1c + (float)(tot - p) * EIc;
    float r = __frcp_rn(denom);
    float wp = E1c * r, wn = EIc * r;
    float4 h = ((const float4*)g_h1)[n * 16 + q];
    uint2 uP, uN;
    ((half2*)&uP)[0] = __floats2half2_rn(wp * h.x, wp * h.y);
    ((half2*)&uP)[1] = __floats2half2_rn(wp * h.z, wp * h.w);
    ((half2*)&uN)[0] = __floats2half2_rn(wn * h.x, wn * h.y);
    ((half2*)&uN)[1] = __floats2half2_rn(wn * h.z, wn * h.w);
    ((uint2*)g_u1p)[n * 16 + q] = uP;
    ((uint2*)g_u1n)[n * 16 + q] = uN;
    if (q == 0) g_cntpos[n] = 0;
}

// ---------------- E2 layer1: fp16 aggregate + bias + relu + fused h2 GEMM ----------------
__global__ void k_e2_64(const float* __restrict__ b1, const float* __restrict__ W2) {
    __shared__ float Wt[64 * 16];   // Wt[k*16+c] = W2[c*64+k]
    __shared__ float so[8][64];
    int t = threadIdx.x;
    for (int i = t; i < 1024; i += 256) {
        int c = i >> 6, k = i & 63;
        Wt[k * 16 + c] = W2[i];
    }
    __syncthreads();
    int w = t >> 5, lane = t & 31;
    int wid = blockIdx.x * 8 + w;
    if (wid >= NN) return;
    int g = lane >> 3, l8 = lane & 7;
    int beg = g_rowbeg[wid], cnt = g_indeg[wid];
    const uint4* up = (const uint4*)g_u1p;
    const uint4* un = (const uint4*)g_u1n;
    float acc[8] = {0.f, 0.f, 0.f, 0.f, 0.f, 0.f, 0.f, 0.f};
    for (int i = g; i < cnt; i += 4) {
        int idx = beg + i;
        int s = g_srt[idx];
        uint4 v = (g_sign[idx] ? up : un)[s * 8 + l8];
        half2* hp = (half2*)&v;
#pragma unroll
        for (int j = 0; j < 4; j++) {
            float2 f = __half22float2(hp[j]);
            acc[2 * j]     += f.x;
            acc[2 * j + 1] += f.y;
        }
    }
    if (g == 0) {  // self loop term
        uint4 v = (g_normsq[wid] > 0.f ? up : un)[wid * 8 + l8];
        half2* hp = (half2*)&v;
#pragma unroll
        for (int j = 0; j < 4; j++) {
            float2 f = __half22float2(hp[j]);
            acc[2 * j]     += f.x;
            acc[2 * j + 1] += f.y;
        }
    }
#pragma unroll
    for (int j = 0; j < 8; j++) {
        acc[j] += __shfl_xor_sync(0xffffffffu, acc[j], 8);
        acc[j] += __shfl_xor_sync(0xffffffffu, acc[j], 16);
    }
    if (g == 0) {
#pragma unroll
        for (int j = 0; j < 8; j++)
            so[w][l8 * 8 + j] = fmaxf(acc[j] + b1[l8 * 8 + j], 0.f);
    }
    __syncwarp();
    // fused h2 = o @ W2^T (16 outputs, k split by half-warp)
    float acc2 = 0.f;
    int c = lane & 15;
    int k0 = (lane >> 4) * 32;
#pragma unroll
    for (int k = 0; k < 32; k++) acc2 += so[w][k0 + k] * Wt[(k0 + k) * 16 + c];
    acc2 += __shfl_xor_sync(0xffffffffu, acc2, 16);
    float nb = __shfl_down_sync(0xffffffffu, acc2, 1);
    if (lane < 16) {
        g_h2[wid * 16 + lane] = acc2;
        if (!(lane & 1)) {
            half2 hh = __floats2half2_rn(acc2, nb);
            g_h2b[wid * 8 + (lane >> 1)] = *(unsigned int*)&hh;
        }
    }
}

// ---------------- E1 layer2: signs + pos counts (fp16 gathers) ----------------
__global__ void k_e1_16() {
    int wid = (blockIdx.x * blockDim.x + threadIdx.x) >> 5;
    if (wid >= NN) return;
    int lane = threadIdx.x & 31;
    int g = lane >> 2, l4 = lane & 3;
    const float4* h2v = (const float4*)g_h2;
    float4 d = h2v[wid * 4 + l4];
    float nq = d.x * d.x + d.y * d.y + d.z * d.z + d.w * d.w;
    nq += __shfl_xor_sync(0xffffffffu, nq, 1);
    nq += __shfl_xor_sync(0xffffffffu, nq, 2);
    if (lane == 0) g_normsq[wid] = nq;
    int beg = g_rowbeg[wid], cnt = g_indeg[wid];
    unsigned gm = 0xFu << (g * 4);
    const uint2* h2bv = (const uint2*)g_h2b;
    for (int i = g; i < cnt; i += 8) {
        int idx = beg + i;
        int s = g_srt[idx];
        uint2 sv = h2bv[s * 4 + l4];
        float2 f0 = __half22float2(*(half2*)&sv.x);
        float2 f1 = __half22float2(*(half2*)&sv.y);
        float a = d.x * f0.x + d.y * f0.y + d.z * f1.x + d.w * f1.y;
        a += __shfl_xor_sync(gm, a, 1);
        a += __shfl_xor_sync(gm, a, 2);
        if (l4 == 0) {
            bool sg = a > 0.f;
            g_sign[idx] = (unsigned char)sg;
            if (sg) atomicAdd(&g_cntpos[s], 1);
        }
    }
}

// ---------------- U2: weights + fp16 message tables (layer 2) ----------------
__global__ void k_u2() {
    int gid = blockIdx.x * blockDim.x + threadIdx.x;
    if (gid >= NN * 4) return;
    int n = gid >> 2, q = gid & 3;
    bool sp = g_normsq[n] > 0.f;
    int p = g_cntpos[n] + (sp ? 1 : 0);
    int tot = g_outdeg[n] + 1;
    const float E1c = 2.718281828459045f;
    const float EIc = 0.36787944117144233f;
    float denom = (float)p * E1c + (float)(tot - p) * EIc;
    float r = __frcp_rn(denom);
    float wp = E1c * r, wn = EIc * r;
    float4 h = ((const float4*)g_h2)[n * 4 + q];
    uint2 uP, uN;
    ((half2*)&uP)[0] = __floats2half2_rn(wp * h.x, wp * h.y);
    ((half2*)&uP)[1] = __floats2half2_rn(wp * h.z, wp * h.w);
    ((half2*)&uN)[0] = __floats2half2_rn(wn * h.x, wn * h.y);
    ((half2*)&uN)[1] = __floats2half2_rn(wn * h.z, wn * h.w);
    ((uint2*)g_u2p)[n * 4 + q] = uP;
    ((uint2*)g_u2n)[n * 4 + q] = uN;
}

// ---------------- E2 layer2: fp16 aggregate + bias + log_softmax ----------------
__global__ void k_e2_16(const float* __restrict__ b2, float* __restrict__ out) {
    int wid = (blockIdx.x * blockDim.x + threadIdx.x) >> 5;
    if (wid >= NN) return;
    int lane = threadIdx.x & 31;
    int g = lane >> 2, l4 = lane & 3;
    int beg = g_rowbeg[wid], cnt = g_indeg[wid];
    const uint2* up = (const uint2*)g_u2p;
    const uint2* un = (const uint2*)g_u2n;
    float4 acc = {0.f, 0.f, 0.f, 0.f};
    for (int i = g; i < cnt; i += 8) {
        int idx = beg + i;
        int s = g_srt[idx];
        uint2 v = (g_sign[idx] ? up : un)[s * 4 + l4];
        float2 f0 = __half22float2(*(half2*)&v.x);
        float2 f1 = __half22float2(*(half2*)&v.y);
        acc.x += f0.x; acc.y += f0.y; acc.z += f1.x; acc.w += f1.y;
    }
    if (g == 0) {  // self
        uint2 v = (g_normsq[wid] > 0.f ? up : un)[wid * 4 + l4];
        float2 f0 = __half22float2(*(half2*)&v.x);
        float2 f1 = __half22float2(*(half2*)&v.y);
        acc.x += f0.x; acc.y += f0.y; acc.z += f1.x; acc.w += f1.y;
    }
#pragma unroll
    for (int o = 4; o < 32; o <<= 1) {
        acc.x += __shfl_xor_sync(0xffffffffu, acc.x, o);
        acc.y += __shfl_xor_sync(0xffffffffu, acc.y, o);
        acc.z += __shfl_xor_sync(0xffffffffu, acc.z, o);
        acc.w += __shfl_xor_sync(0xffffffffu, acc.w, o);
    }
    float4 bb = ((const float4*)b2)[l4];
    float4 v;
    v.x = acc.x + bb.x;
    v.y = acc.y + bb.y;
    v.z = acc.z + bb.z;
    v.w = acc.w + bb.w;
    float m = fmaxf(fmaxf(v.x, v.y), fmaxf(v.z, v.w));
    m = fmaxf(m, __shfl_xor_sync(0xffffffffu, m, 1));
    m = fmaxf(m, __shfl_xor_sync(0xffffffffu, m, 2));
    float e = expf(v.x - m) + expf(v.y - m) + expf(v.z - m) + expf(v.w - m);
    e += __shfl_xor_sync(0xffffffffu, e, 1);
    e += __shfl_xor_sync(0xffffffffu, e, 2);
    float ls = m + logf(e);
    if (lane < 4) {
        float4 rr;
        rr.x = v.x - ls; rr.y = v.y - ls; rr.z = v.z - ls; rr.w = v.w - ls;
        *(float4*)&out[wid * 16 + l4 * 4] = rr;
    }
}

// ---------------- launch ----------------
extern "C" void kernel_launch(void* const* d_in, const int* in_sizes, int n_in,
                              void* d_out, int out_size) {
    (void)in_sizes; (void)n_in; (void)out_size;
    const float* x  = (const float*)d_in[0];
    const int*   ei = (const int*)d_in[1];
    const float* W1 = (const float*)d_in[2];
    const float* b1 = (const float*)d_in[3];
    const float* W2 = (const float*)d_in[4];
    const float* b2 = (const float*)d_in[5];
    float* out = (float*)d_out;

    k_zero<<<(3 * NN + 256) / 256, 256>>>();
    k_prep<<<(NE + 255) / 256, 256>>>(ei);
    k_alloc<<<(NN + 255) / 256, 256>>>();
    k_gemm64<<<(NN + 127) / 128, 256>>>(x, W1);   // 4th launch -> profiled
    k_scatter<<<(NE + 255) / 256, 256>>>(ei);

    k_e1_64<<<(NN + 7) / 8, 256>>>();
    k_u1<<<(NN * 16 + 255) / 256, 256>>>();
    k_e2_64<<<(NN + 7) / 8, 256>>>(b1, W2);

    k_e1_16<<<(NN + 7) / 8, 256>>>();
    k_u2<<<(NN * 4 + 255) / 256, 256>>>();
    k_e2_16<<<(NN + 7) / 8, 256>>>(b2, out);
}

// round 7
// speedup vs baseline: 1.0445x; 1.0445x over previous
#include <cuda_runtime.h>
#include <cuda_fp16.h>

#define NN 100000
#define NE 1600000

// ---------------- device scratch (zero-initialized at load; kernels restore zeros at end of each call) ----------------
__device__ int g_srt[NE];
__device__ unsigned char g_sign[NE];
__device__ int g_cnt3[3 * NN + 1];   // [0,NN)=indeg  [NN,2NN)=outdeg  [2NN,3NN)=cntpos  [3NN]=ctr
__device__ int g_rowbeg[NN];
__device__ int g_wptr[NN];
__device__ float g_normsq[NN];
__device__ float g_h1[NN * 64];
__device__ float g_h2[NN * 16];
__device__ uint4 g_h1b[NN * 8];          // fp16 h1, 128B/row
__device__ unsigned int g_h2b[NN * 8];   // fp16 h2, 32B/row
__device__ unsigned int g_u1p[NN * 32];  // 64 half per node
__device__ unsigned int g_u1n[NN * 32];
__device__ unsigned int g_u2p[NN * 8];   // 16 half per node
__device__ unsigned int g_u2n[NN * 8];

#define g_indeg  (g_cnt3)
#define g_outdeg (g_cnt3 + NN)
#define g_cntpos (g_cnt3 + 2 * NN)

// ---------------- degrees: 4 edges/thread ----------------
__global__ void k_prep(const int* __restrict__ ei) {
    int t = blockIdx.x * blockDim.x + threadIdx.x;
    int e0 = t * 4;
    if (e0 >= NE) return;
    int4 s = *(const int4*)&ei[e0];
    int4 d = *(const int4*)&ei[NE + e0];
    atomicAdd(&g_outdeg[s.x], 1);
    atomicAdd(&g_outdeg[s.y], 1);
    atomicAdd(&g_outdeg[s.z], 1);
    atomicAdd(&g_outdeg[s.w], 1);
    atomicAdd(&g_indeg[d.x], 1);
    atomicAdd(&g_indeg[d.y], 1);
    atomicAdd(&g_indeg[d.z], 1);
    atomicAdd(&g_indeg[d.w], 1);
}

// ---------------- CSR offsets via block-aggregated atomic ----------------
__global__ void k_alloc() {
    __shared__ int warpsum[8];
    __shared__ int sbase;
    int i = blockIdx.x * 256 + threadIdx.x;
    int v = (i < NN) ? g_indeg[i] : 0;
    int lane = threadIdx.x & 31, w = threadIdx.x >> 5;
    int incl = v;
#pragma unroll
    for (int o = 1; o < 32; o <<= 1) {
        int u = __shfl_up_sync(0xffffffffu, incl, o);
        if (lane >= o) incl += u;
    }
    if (lane == 31) warpsum[w] = incl;
    __syncthreads();
    if (w == 0) {
        int s = (lane < 8) ? warpsum[lane] : 0;
#pragma unroll
        for (int o = 1; o < 8; o <<= 1) {
            int u = __shfl_up_sync(0xffffffffu, s, o);
            if (lane >= o) s += u;
        }
        if (lane < 8) warpsum[lane] = s;
        if (lane == 7) sbase = atomicAdd(&g_cnt3[3 * NN], s);
    }
    __syncthreads();
    int excl = incl - v + (w ? warpsum[w - 1] : 0);
    if (i < NN) {
        int r = sbase + excl;
        g_rowbeg[i] = r;
        g_wptr[i] = r;
    }
}

// ---------------- scatter: 4 edges/thread ----------------
__global__ void k_scatter(const int* __restrict__ ei) {
    int t = blockIdx.x * blockDim.x + threadIdx.x;
    int e0 = t * 4;
    if (e0 >= NE) return;
    int4 s = *(const int4*)&ei[e0];
    int4 d = *(const int4*)&ei[NE + e0];
    int p0 = atomicAdd(&g_wptr[d.x], 1);
    int p1 = atomicAdd(&g_wptr[d.y], 1);
    int p2 = atomicAdd(&g_wptr[d.z], 1);
    int p3 = atomicAdd(&g_wptr[d.w], 1);
    g_srt[p0] = s.x;
    g_srt[p1] = s.y;
    g_srt[p2] = s.z;
    g_srt[p3] = s.w;
}

// ---------------- GEMM: h1 = x @ W1^T ; 128 rows/block, thread = 4 rows x 8 cols, k chunked by 4 ----------------
__global__ void __launch_bounds__(256) k_gemm64(const float* __restrict__ x, const float* __restrict__ W) {
    __shared__ float Ws[64 * 64];       // Ws[k*64+c] = W[c*64+k]
    __shared__ float sx[128 * 68];      // 128 rows, stride 68 floats
    int t = threadIdx.x;
    for (int i = t; i < 4096; i += 256) {
        int c = i >> 6, k = i & 63;
        Ws[k * 64 + c] = W[i];
    }
    int r0 = blockIdx.x * 128;
    int nrows = NN - r0; if (nrows > 128) nrows = 128;
    for (int i = t; i < nrows * 16; i += 256) {
        int row = i >> 4, cc = i & 15;
        float4 v = ((const float4*)x)[(r0 + row) * 16 + cc];
        *(float4*)&sx[row * 68 + cc * 4] = v;
    }
    __syncthreads();
    int tc = t & 7;      // col octet
    int tr = t >> 3;     // row quad
    int rbase = tr * 4;
    float a[4][8];
#pragma unroll
    for (int r = 0; r < 4; r++)
#pragma unroll
        for (int c = 0; c < 8; c++) a[r][c] = 0.f;
#pragma unroll
    for (int k = 0; k < 64; k += 4) {
        float4 xr[4];
#pragma unroll
        for (int r = 0; r < 4; r++) xr[r] = *(const float4*)&sx[(rbase + r) * 68 + k];
#pragma unroll
        for (int kk = 0; kk < 4; kk++) {
            float4 w0 = *(const float4*)&Ws[(k + kk) * 64 + tc * 8];
            float4 w1 = *(const float4*)&Ws[(k + kk) * 64 + tc * 8 + 4];
#pragma unroll
            for (int r = 0; r < 4; r++) {
                float xv = (kk == 0) ? xr[r].x : (kk == 1) ? xr[r].y : (kk == 2) ? xr[r].z : xr[r].w;
                a[r][0] += xv * w0.x; a[r][1] += xv * w0.y;
                a[r][2] += xv * w0.z; a[r][3] += xv * w0.w;
                a[r][4] += xv * w1.x; a[r][5] += xv * w1.y;
                a[r][6] += xv * w1.z; a[r][7] += xv * w1.w;
            }
        }
    }
#pragma unroll
    for (int r = 0; r < 4; r++) {
        int row = r0 + rbase + r;
        if (rbase + r < nrows) {
            float4 o0 = {a[r][0], a[r][1], a[r][2], a[r][3]};
            float4 o1 = {a[r][4], a[r][5], a[r][6], a[r][7]};
            ((float4*)g_h1)[row * 16 + tc * 2]     = o0;
            ((float4*)g_h1)[row * 16 + tc * 2 + 1] = o1;
            uint4 hb;
            ((half2*)&hb)[0] = __floats2half2_rn(a[r][0], a[r][1]);
            ((half2*)&hb)[1] = __floats2half2_rn(a[r][2], a[r][3]);
            ((half2*)&hb)[2] = __floats2half2_rn(a[r][4], a[r][5]);
            ((half2*)&hb)[3] = __floats2half2_rn(a[r][6], a[r][7]);
            g_h1b[row * 8 + tc] = hb;
        }
    }
}

// ---------------- helpers ----------------
__device__ __forceinline__ float dot8h(float4 d0, float4 d1, uint4 v) {
    float2 f0 = __half22float2(((half2*)&v)[0]);
    float2 f1 = __half22float2(((half2*)&v)[1]);
    float2 f2 = __half22float2(((half2*)&v)[2]);
    float2 f3 = __half22float2(((half2*)&v)[3]);
    return d0.x * f0.x + d0.y * f0.y + d0.z * f1.x + d0.w * f1.y
         + d1.x * f2.x + d1.y * f2.y + d1.z * f3.x + d1.w * f3.y;
}

// ---------------- E1 layer1: signs + pos counts (fp16 gathers, unroll 2) ----------------
__global__ void k_e1_64() {
    int wid = (blockIdx.x * blockDim.x + threadIdx.x) >> 5;
    if (wid >= NN) return;
    int lane = threadIdx.x & 31;
    int g = lane >> 3, l8 = lane & 7;
    const float4* h1v = (const float4*)g_h1;
    float4 d0 = h1v[wid * 16 + l8 * 2];
    float4 d1 = h1v[wid * 16 + l8 * 2 + 1];
    float nq = d0.x * d0.x + d0.y * d0.y + d0.z * d0.z + d0.w * d0.w
             + d1.x * d1.x + d1.y * d1.y + d1.z * d1.z + d1.w * d1.w;
#pragma unroll
    for (int o = 4; o; o >>= 1) nq += __shfl_xor_sync(0xffffffffu, nq, o);
    if (lane == 0) g_normsq[wid] = nq;
    int beg = g_rowbeg[wid], cnt = g_indeg[wid];
    unsigned gm = 0xFFu << (g * 8);
    int i = g;
    for (; i + 4 < cnt; i += 8) {
        int idx0 = beg + i, idx1 = beg + i + 4;
        int s0 = g_srt[idx0];
        int s1 = g_srt[idx1];
        uint4 v0 = g_h1b[s0 * 8 + l8];
        uint4 v1 = g_h1b[s1 * 8 + l8];
        float a0 = dot8h(d0, d1, v0);
        float a1 = dot8h(d0, d1, v1);
        a0 += __shfl_xor_sync(gm, a0, 1);
        a1 += __shfl_xor_sync(gm, a1, 1);
        a0 += __shfl_xor_sync(gm, a0, 2);
        a1 += __shfl_xor_sync(gm, a1, 2);
        a0 += __shfl_xor_sync(gm, a0, 4);
        a1 += __shfl_xor_sync(gm, a1, 4);
        if (l8 == 0) {
            bool sg0 = a0 > 0.f, sg1 = a1 > 0.f;
            g_sign[idx0] = (unsigned char)sg0;
            g_sign[idx1] = (unsigned char)sg1;
            if (sg0) atomicAdd(&g_cntpos[s0], 1);
            if (sg1) atomicAdd(&g_cntpos[s1], 1);
        }
    }
    if (i < cnt) {
        int idx = beg + i;
        int s = g_srt[idx];
        uint4 v = g_h1b[s * 8 + l8];
        float a = dot8h(d0, d1, v);
        a += __shfl_xor_sync(gm, a, 1);
        a += __shfl_xor_sync(gm, a, 2);
        a += __shfl_xor_sync(gm, a, 4);
        if (l8 == 0) {
            bool sg = a > 0.f;
            g_sign[idx] = (unsigned char)sg;
            if (sg) atomicAdd(&g_cntpos[s], 1);
        }
    }
}

// ---------------- U1: weights + fp16 message tables (layer 1); resets ctr+cntpos ----------------
__global__ void k_u1() {
    int gid = blockIdx.x * blockDim.x + threadIdx.x;
    if (gid >= NN * 16) return;
    int n = gid >> 4, q = gid & 15;
    bool sp = g_normsq[n] > 0.f;
    int p = g_cntpos[n] + (sp ? 1 : 0);
    int tot = g_outdeg[n] + 1;
    const float E1c = 2.718281828459045f;
    const float EIc = 0.36787944117144233f;
    float denom = (float)p * E1c + (float)(tot - p) * EIc;
    float r = __frcp_rn(denom);
    float wp = E1c * r, wn = EIc * r;
    float4 h = ((const float4*)g_h1)[n * 16 + q];
    uint2 uP, uN;
    ((half2*)&uP)[0] = __floats2half2_rn(wp * h.x, wp * h.y);
    ((half2*)&uP)[1] = __floats2half2_rn(wp * h.z, wp * h.w);
    ((half2*)&uN)[0] = __floats2half2_rn(wn * h.x, wn * h.y);
    ((half2*)&uN)[1] = __floats2half2_rn(wn * h.z, wn * h.w);
    ((uint2*)g_u1p)[n * 16 + q] = uP;
    ((uint2*)g_u1n)[n * 16 + q] = uN;
    if (q == 0) g_cntpos[n] = 0;
    if (gid == 0) g_cnt3[3 * NN] = 0;
}

// ---------------- E2 layer1: fp16 aggregate (unroll 2) + bias + relu + fused h2 GEMM ----------------
__global__ void k_e2_64(const float* __restrict__ b1, const float* __restrict__ W2) {
    __shared__ float Wt[64 * 16];   // Wt[k*16+c] = W2[c*64+k]
    __shared__ float so[8][64];
    int t = threadIdx.x;
    for (int i = t; i < 1024; i += 256) {
        int c = i >> 6, k = i & 63;
        Wt[k * 16 + c] = W2[i];
    }
    __syncthreads();
    int w = t >> 5, lane = t & 31;
    int wid = blockIdx.x * 8 + w;
    if (wid >= NN) return;
    int g = lane >> 3, l8 = lane & 7;
    int beg = g_rowbeg[wid], cnt = g_indeg[wid];
    const uint4* up = (const uint4*)g_u1p;
    const uint4* un = (const uint4*)g_u1n;
    float acc[8] = {0.f, 0.f, 0.f, 0.f, 0.f, 0.f, 0.f, 0.f};
    int i = g;
    for (; i + 4 < cnt; i += 8) {
        int idx0 = beg + i, idx1 = beg + i + 4;
        int s0 = g_srt[idx0];
        int s1 = g_srt[idx1];
        unsigned char sg0 = g_sign[idx0], sg1 = g_sign[idx1];
        uint4 v0 = (sg0 ? up : un)[s0 * 8 + l8];
        uint4 v1 = (sg1 ? up : un)[s1 * 8 + l8];
        half2* h0 = (half2*)&v0;
        half2* h1 = (half2*)&v1;
#pragma unroll
        for (int j = 0; j < 4; j++) {
            float2 f0 = __half22float2(h0[j]);
            float2 f1 = __half22float2(h1[j]);
            acc[2 * j]     += f0.x + f1.x;
            acc[2 * j + 1] += f0.y + f1.y;
        }
    }
    if (i < cnt) {
        int idx = beg + i;
        int s = g_srt[idx];
        uint4 v = (g_sign[idx] ? up : un)[s * 8 + l8];
        half2* hp = (half2*)&v;
#pragma unroll
        for (int j = 0; j < 4; j++) {
            float2 f = __half22float2(hp[j]);
            acc[2 * j]     += f.x;
            acc[2 * j + 1] += f.y;
        }
    }
    if (g == 0) {  // self loop term
        uint4 v = (g_normsq[wid] > 0.f ? up : un)[wid * 8 + l8];
        half2* hp = (half2*)&v;
#pragma unroll
        for (int j = 0; j < 4; j++) {
            float2 f = __half22float2(hp[j]);
            acc[2 * j]     += f.x;
            acc[2 * j + 1] += f.y;
        }
    }
#pragma unroll
    for (int j = 0; j < 8; j++) {
        acc[j] += __shfl_xor_sync(0xffffffffu, acc[j], 8);
        acc[j] += __shfl_xor_sync(0xffffffffu, acc[j], 16);
    }
    if (g == 0) {
#pragma unroll
        for (int j = 0; j < 8; j++)
            so[w][l8 * 8 + j] = fmaxf(acc[j] + b1[l8 * 8 + j], 0.f);
    }
    __syncwarp();
    // fused h2 = o @ W2^T (16 outputs, k split by half-warp)
    float acc2 = 0.f;
    int c = lane & 15;
    int k0 = (lane >> 4) * 32;
#pragma unroll
    for (int k = 0; k < 32; k++) acc2 += so[w][k0 + k] * Wt[(k0 + k) * 16 + c];
    acc2 += __shfl_xor_sync(0xffffffffu, acc2, 16);
    float nb = __shfl_down_sync(0xffffffffu, acc2, 1);
    if (lane < 16) {
        g_h2[wid * 16 + lane] = acc2;
        if (!(lane & 1)) {
            half2 hh = __floats2half2_rn(acc2, nb);
            g_h2b[wid * 8 + (lane >> 1)] = *(unsigned int*)&hh;
        }
    }
}

// ---------------- E1 layer2: signs + pos counts (fp16 gathers, unroll 2) ----------------
__global__ void k_e1_16() {
    int wid = (blockIdx.x * blockDim.x + threadIdx.x) >> 5;
    if (wid >= NN) return;
    int lane = threadIdx.x & 31;
    int g = lane >> 2, l4 = lane & 3;
    const float4* h2v = (const float4*)g_h2;
    float4 d = h2v[wid * 4 + l4];
    float nq = d.x * d.x + d.y * d.y + d.z * d.z + d.w * d.w;
    nq += __shfl_xor_sync(0xffffffffu, nq, 1);
    nq += __shfl_xor_sync(0xffffffffu, nq, 2);
    if (lane == 0) g_normsq[wid] = nq;
    int beg = g_rowbeg[wid], cnt = g_indeg[wid];
    unsigned gm = 0xFu << (g * 4);
    const uint2* h2bv = (const uint2*)g_h2b;
    int i = g;
    for (; i + 8 < cnt; i += 16) {
        int idx0 = beg + i, idx1 = beg + i + 8;
        int s0 = g_srt[idx0];
        int s1 = g_srt[idx1];
        uint2 sv0 = h2bv[s0 * 4 + l4];
        uint2 sv1 = h2bv[s1 * 4 + l4];
        float2 p0 = __half22float2(*(half2*)&sv0.x);
        float2 p1 = __half22float2(*(half2*)&sv0.y);
        float2 q0 = __half22float2(*(half2*)&sv1.x);
        float2 q1 = __half22float2(*(half2*)&sv1.y);
        float a0 = d.x * p0.x + d.y * p0.y + d.z * p1.x + d.w * p1.y;
        float a1 = d.x * q0.x + d.y * q0.y + d.z * q1.x + d.w * q1.y;
        a0 += __shfl_xor_sync(gm, a0, 1);
        a1 += __shfl_xor_sync(gm, a1, 1);
        a0 += __shfl_xor_sync(gm, a0, 2);
        a1 += __shfl_xor_sync(gm, a1, 2);
        if (l4 == 0) {
            bool sg0 = a0 > 0.f, sg1 = a1 > 0.f;
            g_sign[idx0] = (unsigned char)sg0;
            g_sign[idx1] = (unsigned char)sg1;
            if (sg0) atomicAdd(&g_cntpos[s0], 1);
            if (sg1) atomicAdd(&g_cntpos[s1], 1);
        }
    }
    if (i < cnt) {
        int idx = beg + i;
        int s = g_srt[idx];
        uint2 sv = h2bv[s * 4 + l4];
        float2 f0 = __half22float2(*(half2*)&sv.x);
        float2 f1 = __half22float2(*(half2*)&sv.y);
        float a = d.x * f0.x + d.y * f0.y + d.z * f1.x + d.w * f1.y;
        a += __shfl_xor_sync(gm, a, 1);
        a += __shfl_xor_sync(gm, a, 2);
        if (l4 == 0) {
            bool sg = a > 0.f;
            g_sign[idx] = (unsigned char)sg;
            if (sg) atomicAdd(&g_cntpos[s], 1);
        }
    }
}

// ---------------- U2: weights + fp16 message tables (layer 2); resets outdeg+cntpos ----------------
__global__ void k_u2() {
    int gid = blockIdx.x * blockDim.x + threadIdx.x;
    if (gid >= NN * 4) return;
    int n = gid >> 2, q = gid & 3;
    bool sp = g_normsq[n] > 0.f;
    int p = g_cntpos[n] + (sp ? 1 : 0);
    int tot = g_outdeg[n] + 1;
    const float E1c = 2.718281828459045f;
    const float EIc = 0.36787944117144233f;
    float denom = (float)p * E1c + (float)(tot - p) * EIc;
    float r = __frcp_rn(denom);
    float wp = E1c * r, wn = EIc * r;
    float4 h = ((const float4*)g_h2)[n * 4 + q];
    uint2 uP, uN;
    ((half2*)&uP)[0] = __floats2half2_rn(wp * h.x, wp * h.y);
    ((half2*)&uP)[1] = __floats2half2_rn(wp * h.z, wp * h.w);
    ((half2*)&uN)[0] = __floats2half2_rn(wn * h.x, wn * h.y);
    ((half2*)&uN)[1] = __floats2half2_rn(wn * h.z, wn * h.w);
    ((uint2*)g_u2p)[n * 4 + q] = uP;
    ((uint2*)g_u2n)[n * 4 + q] = uN;
    if (q == 0) { g_cntpos[n] = 0; g_outdeg[n] = 0; }
}

// ---------------- E2 layer2: fp16 aggregate (unroll 2) + bias + log_softmax; resets indeg ----------------
__global__ void k_e2_16(const float* __restrict__ b2, float* __restrict__ out) {
    int wid = (blockIdx.x * blockDim.x + threadIdx.x) >> 5;
    if (wid >= NN) return;
    int lane = threadIdx.x & 31;
    int g = lane >> 2, l4 = lane & 3;
    int beg = g_rowbeg[wid], cnt = g_indeg[wid];
    const uint2* up = (const uint2*)g_u2p;
    const uint2* un = (const uint2*)g_u2n;
    float4 acc = {0.f, 0.f, 0.f, 0.f};
    int i = g;
    for (; i + 8 < cnt; i += 16) {
        int idx0 = beg + i, idx1 = beg + i + 8;
        int s0 = g_srt[idx0];
        int s1 = g_srt[idx1];
        unsigned char sg0 = g_sign[idx0], sg1 = g_sign[idx1];
        uint2 v0 = (sg0 ? up : un)[s0 * 4 + l4];
        uint2 v1 = (sg1 ? up : un)[s1 * 4 + l4];
        float2 p0 = __half22float2(*(half2*)&v0.x);
        float2 p1 = __half22float2(*(half2*)&v0.y);
        float2 q0 = __half22float2(*(half2*)&v1.x);
        float2 q1 = __half22float2(*(half2*)&v1.y);
        acc.x += p0.x + q0.x; acc.y += p0.y + q0.y;
        acc.z += p1.x + q1.x; acc.w += p1.y + q1.y;
    }
    if (i < cnt) {
        int idx = beg + i;
        int s = g_srt[idx];
        uint2 v = (g_sign[idx] ? up : un)[s * 4 + l4];
        float2 f0 = __half22float2(*(half2*)&v.x);
        float2 f1 = __half22float2(*(half2*)&v.y);
        acc.x += f0.x; acc.y += f0.y; acc.z += f1.x; acc.w += f1.y;
    }
    if (g == 0) {  // self
        uint2 v = (g_normsq[wid] > 0.f ? up : un)[wid * 4 + l4];
        float2 f0 = __half22float2(*(half2*)&v.x);
        float2 f1 = __half22float2(*(half2*)&v.y);
        acc.x += f0.x; acc.y += f0.y; acc.z += f1.x; acc.w += f1.y;
    }
#pragma unroll
    for (int o = 4; o < 32; o <<= 1) {
        acc.x += __shfl_xor_sync(0xffffffffu, acc.x, o);
        acc.y += __shfl_xor_sync(0xffffffffu, acc.y, o);
        acc.z += __shfl_xor_sync(0xffffffffu, acc.z, o);
        acc.w += __shfl_xor_sync(0xffffffffu, acc.w, o);
    }
    float4 bb = ((const float4*)b2)[l4];
    float4 v;
    v.x = acc.x + bb.x;
    v.y = acc.y + bb.y;
    v.z = acc.z + bb.z;
    v.w = acc.w + bb.w;
    float m = fmaxf(fmaxf(v.x, v.y), fmaxf(v.z, v.w));
    m = fmaxf(m, __shfl_xor_sync(0xffffffffu, m, 1));
    m = fmaxf(m, __shfl_xor_sync(0xffffffffu, m, 2));
    float e = expf(v.x - m) + expf(v.y - m) + expf(v.z - m) + expf(v.w - m);
    e += __shfl_xor_sync(0xffffffffu, e, 1);
    e += __shfl_xor_sync(0xffffffffu, e, 2);
    float ls = m + logf(e);
    if (lane < 4) {
        float4 rr;
        rr.x = v.x - ls; rr.y = v.y - ls; rr.z = v.z - ls; rr.w = v.w - ls;
        *(float4*)&out[wid * 16 + l4 * 4] = rr;
    }
    if (lane == 0) g_indeg[wid] = 0;  // reset for next call
}

// ---------------- launch ----------------
extern "C" void kernel_launch(void* const* d_in, const int* in_sizes, int n_in,
                              void* d_out, int out_size) {
    (void)in_sizes; (void)n_in; (void)out_size;
    const float* x  = (const float*)d_in[0];
    const int*   ei = (const int*)d_in[1];
    const float* W1 = (const float*)d_in[2];
    const float* b1 = (const float*)d_in[3];
    const float* W2 = (const float*)d_in[4];
    const float* b2 = (const float*)d_in[5];
    float* out = (float*)d_out;

    k_prep<<<(NE / 4 + 255) / 256, 256>>>(ei);
    k_alloc<<<(NN + 255) / 256, 256>>>();
    k_gemm64<<<(NN + 127) / 128, 256>>>(x, W1);
    k_scatter<<<(NE / 4 + 255) / 256, 256>>>(ei);   // 4th launch -> profiled

    k_e1_64<<<(NN + 7) / 8, 256>>>();
    k_u1<<<(NN * 16 + 255) / 256, 256>>>();
    k_e2_64<<<(NN + 7) / 8, 256>>>(b1, W2);

    k_e1_16<<<(NN + 7) / 8, 256>>>();
    k_u2<<<(NN * 4 + 255) / 256, 256>>>();
    k_e2_16<<<(NN + 7) / 8, 256>>>(b2, out);
}

// round 8
// speedup vs baseline: 1.0927x; 1.0462x over previous
#include <cuda_runtime.h>
#include <cuda_fp16.h>

#define NN 100000
#define NE 1600000
#define GEMM_BLOCKS ((NN + 127) / 128)          // 782
#define SCAT_BLOCKS ((NE / 4 + 255) / 256)      // 1563

// ---------------- device scratch (zero-initialized at load; kernels restore zeros each call) ----------------
__device__ int g_srt[NE];
__device__ unsigned char g_sign[NE];
__device__ int g_cnt3[3 * NN + 1];   // [0,NN)=indeg  [NN,2NN)=outdeg  [2NN,3NN)=cntpos  [3NN]=ctr
__device__ int g_rowbeg[NN];
__device__ int g_wptr[NN];
__device__ float g_normsq[NN];
__device__ float g_h1[NN * 64];
__device__ float g_h2[NN * 16];
__device__ uint4 g_h1b[NN * 8];          // fp16 h1, 128B/row
__device__ unsigned int g_h2b[NN * 8];   // fp16 h2, 32B/row
__device__ unsigned int g_u1p[NN * 32];  // 64 half per node
__device__ unsigned int g_u1n[NN * 32];
__device__ unsigned int g_u2p[NN * 8];   // 16 half per node
__device__ unsigned int g_u2n[NN * 8];

#define g_indeg  (g_cnt3)
#define g_outdeg (g_cnt3 + NN)
#define g_cntpos (g_cnt3 + 2 * NN)

// ---------------- prep: indeg only, 4 edges/thread ----------------
__global__ void k_prep(const int* __restrict__ ei) {
    int t = blockIdx.x * blockDim.x + threadIdx.x;
    int e0 = t * 4;
    if (e0 >= NE) return;
    int4 d = *(const int4*)&ei[NE + e0];
    atomicAdd(&g_indeg[d.x], 1);
    atomicAdd(&g_indeg[d.y], 1);
    atomicAdd(&g_indeg[d.z], 1);
    atomicAdd(&g_indeg[d.w], 1);
}

// ---------------- CSR offsets via block-aggregated atomic ----------------
__global__ void k_alloc() {
    __shared__ int warpsum[8];
    __shared__ int sbase;
    int i = blockIdx.x * 256 + threadIdx.x;
    int v = (i < NN) ? g_indeg[i] : 0;
    int lane = threadIdx.x & 31, w = threadIdx.x >> 5;
    int incl = v;
#pragma unroll
    for (int o = 1; o < 32; o <<= 1) {
        int u = __shfl_up_sync(0xffffffffu, incl, o);
        if (lane >= o) incl += u;
    }
    if (lane == 31) warpsum[w] = incl;
    __syncthreads();
    if (w == 0) {
        int s = (lane < 8) ? warpsum[lane] : 0;
#pragma unroll
        for (int o = 1; o < 8; o <<= 1) {
            int u = __shfl_up_sync(0xffffffffu, s, o);
            if (lane >= o) s += u;
        }
        if (lane < 8) warpsum[lane] = s;
        if (lane == 7) sbase = atomicAdd(&g_cnt3[3 * NN], s);
    }
    __syncthreads();
    int excl = incl - v + (w ? warpsum[w - 1] : 0);
    if (i < NN) {
        int r = sbase + excl;
        g_rowbeg[i] = r;
        g_wptr[i] = r;
    }
}

// ---------------- merged: GEMM blocks [0,782) + scatter/outdeg blocks [782, 2345) ----------------
__global__ void __launch_bounds__(256) k_gs(const float* __restrict__ x, const float* __restrict__ W,
                                            const int* __restrict__ ei) {
    __shared__ float Ws[64 * 64];       // Ws[k*64+c] = W[c*64+k]
    __shared__ float sx[128 * 68];      // 128 rows, stride 68 floats
    int t = threadIdx.x;
    if (blockIdx.x >= GEMM_BLOCKS) {
        // ---- scatter + outdeg ----
        int b = blockIdx.x - GEMM_BLOCKS;
        int e0 = (b * 256 + t) * 4;
        if (e0 >= NE) return;
        int4 s = *(const int4*)&ei[e0];
        int4 d = *(const int4*)&ei[NE + e0];
        atomicAdd(&g_outdeg[s.x], 1);
        atomicAdd(&g_outdeg[s.y], 1);
        atomicAdd(&g_outdeg[s.z], 1);
        atomicAdd(&g_outdeg[s.w], 1);
        int p0 = atomicAdd(&g_wptr[d.x], 1);
        int p1 = atomicAdd(&g_wptr[d.y], 1);
        int p2 = atomicAdd(&g_wptr[d.z], 1);
        int p3 = atomicAdd(&g_wptr[d.w], 1);
        g_srt[p0] = s.x;
        g_srt[p1] = s.y;
        g_srt[p2] = s.z;
        g_srt[p3] = s.w;
        return;
    }
    // ---- GEMM: 128 rows/block, thread = 4 rows x 8 cols, k chunked by 4 ----
    for (int i = t; i < 4096; i += 256) {
        int c = i >> 6, k = i & 63;
        Ws[k * 64 + c] = W[i];
    }
    int r0 = blockIdx.x * 128;
    int nrows = NN - r0; if (nrows > 128) nrows = 128;
    for (int i = t; i < nrows * 16; i += 256) {
        int row = i >> 4, cc = i & 15;
        float4 v = ((const float4*)x)[(r0 + row) * 16 + cc];
        *(float4*)&sx[row * 68 + cc * 4] = v;
    }
    __syncthreads();
    int tc = t & 7;
    int tr = t >> 3;
    int rbase = tr * 4;
    float a[4][8];
#pragma unroll
    for (int r = 0; r < 4; r++)
#pragma unroll
        for (int c = 0; c < 8; c++) a[r][c] = 0.f;
#pragma unroll
    for (int k = 0; k < 64; k += 4) {
        float4 xr[4];
#pragma unroll
        for (int r = 0; r < 4; r++) xr[r] = *(const float4*)&sx[(rbase + r) * 68 + k];
#pragma unroll
        for (int kk = 0; kk < 4; kk++) {
            float4 w0 = *(const float4*)&Ws[(k + kk) * 64 + tc * 8];
            float4 w1 = *(const float4*)&Ws[(k + kk) * 64 + tc * 8 + 4];
#pragma unroll
            for (int r = 0; r < 4; r++) {
                float xv = (kk == 0) ? xr[r].x : (kk == 1) ? xr[r].y : (kk == 2) ? xr[r].z : xr[r].w;
                a[r][0] += xv * w0.x; a[r][1] += xv * w0.y;
                a[r][2] += xv * w0.z; a[r][3] += xv * w0.w;
                a[r][4] += xv * w1.x; a[r][5] += xv * w1.y;
                a[r][6] += xv * w1.z; a[r][7] += xv * w1.w;
            }
        }
    }
#pragma unroll
    for (int r = 0; r < 4; r++) {
        int row = r0 + rbase + r;
        if (rbase + r < nrows) {
            float4 o0 = {a[r][0], a[r][1], a[r][2], a[r][3]};
            float4 o1 = {a[r][4], a[r][5], a[r][6], a[r][7]};
            ((float4*)g_h1)[row * 16 + tc * 2]     = o0;
            ((float4*)g_h1)[row * 16 + tc * 2 + 1] = o1;
            uint4 hb;
            ((half2*)&hb)[0] = __floats2half2_rn(a[r][0], a[r][1]);
            ((half2*)&hb)[1] = __floats2half2_rn(a[r][2], a[r][3]);
            ((half2*)&hb)[2] = __floats2half2_rn(a[r][4], a[r][5]);
            ((half2*)&hb)[3] = __floats2half2_rn(a[r][6], a[r][7]);
            g_h1b[row * 8 + tc] = hb;
        }
    }
}

// ---------------- helpers ----------------
__device__ __forceinline__ float dot8h(float4 d0, float4 d1, uint4 v) {
    float2 f0 = __half22float2(((half2*)&v)[0]);
    float2 f1 = __half22float2(((half2*)&v)[1]);
    float2 f2 = __half22float2(((half2*)&v)[2]);
    float2 f3 = __half22float2(((half2*)&v)[3]);
    return d0.x * f0.x + d0.y * f0.y + d0.z * f1.x + d0.w * f1.y
         + d1.x * f2.x + d1.y * f2.y + d1.z * f3.x + d1.w * f3.y;
}

// ---------------- E1 layer1: signs + pos counts (fp16 gathers, unroll 4) ----------------
__global__ void k_e1_64() {
    int wid = (blockIdx.x * blockDim.x + threadIdx.x) >> 5;
    if (wid >= NN) return;
    int lane = threadIdx.x & 31;
    int g = lane >> 3, l8 = lane & 7;
    const float4* h1v = (const float4*)g_h1;
    float4 d0 = h1v[wid * 16 + l8 * 2];
    float4 d1 = h1v[wid * 16 + l8 * 2 + 1];
    float nq = d0.x * d0.x + d0.y * d0.y + d0.z * d0.z + d0.w * d0.w
             + d1.x * d1.x + d1.y * d1.y + d1.z * d1.z + d1.w * d1.w;
#pragma unroll
    for (int o = 4; o; o >>= 1) nq += __shfl_xor_sync(0xffffffffu, nq, o);
    if (lane == 0) g_normsq[wid] = nq;
    int beg = g_rowbeg[wid], cnt = g_indeg[wid];
    unsigned gm = 0xFFu << (g * 8);
    int i = g;
    for (; i + 12 < cnt; i += 16) {
        int idx[4], s[4];
        uint4 v[4];
        float a[4];
#pragma unroll
        for (int j = 0; j < 4; j++) { idx[j] = beg + i + j * 4; s[j] = g_srt[idx[j]]; }
#pragma unroll
        for (int j = 0; j < 4; j++) v[j] = g_h1b[s[j] * 8 + l8];
#pragma unroll
        for (int j = 0; j < 4; j++) a[j] = dot8h(d0, d1, v[j]);
#pragma unroll
        for (int o = 1; o <= 4; o <<= 1)
#pragma unroll
            for (int j = 0; j < 4; j++) a[j] += __shfl_xor_sync(gm, a[j], o);
        if (l8 == 0) {
#pragma unroll
            for (int j = 0; j < 4; j++) {
                bool sg = a[j] > 0.f;
                g_sign[idx[j]] = (unsigned char)sg;
                if (sg) atomicAdd(&g_cntpos[s[j]], 1);
            }
        }
    }
    for (; i < cnt; i += 4) {
        int idx = beg + i;
        int s = g_srt[idx];
        uint4 v = g_h1b[s * 8 + l8];
        float a = dot8h(d0, d1, v);
        a += __shfl_xor_sync(gm, a, 1);
        a += __shfl_xor_sync(gm, a, 2);
        a += __shfl_xor_sync(gm, a, 4);
        if (l8 == 0) {
            bool sg = a > 0.f;
            g_sign[idx] = (unsigned char)sg;
            if (sg) atomicAdd(&g_cntpos[s], 1);
        }
    }
}

// ---------------- U1: weights + fp16 message tables (layer 1); resets ctr+cntpos ----------------
__global__ void k_u1() {
    int gid = blockIdx.x * blockDim.x + threadIdx.x;
    if (gid >= NN * 16) return;
    int n = gid >> 4, q = gid & 15;
    bool sp = g_normsq[n] > 0.f;
    int p = g_cntpos[n] + (sp ? 1 : 0);
    int tot = g_outdeg[n] + 1;
    const float E1c = 2.718281828459045f;
    const float EIc = 0.36787944117144233f;
    float denom = (float)p * E1c + (float)(tot - p) * EIc;
    float r = __frcp_rn(denom);
    float wp = E1c * r, wn = EIc * r;
    float4 h = ((const float4*)g_h1)[n * 16 + q];
    uint2 uP, uN;
    ((half2*)&uP)[0] = __floats2half2_rn(wp * h.x, wp * h.y);
    ((half2*)&uP)[1] = __floats2half2_rn(wp * h.z, wp * h.w);
    ((half2*)&uN)[0] = __floats2half2_rn(wn * h.x, wn * h.y);
    ((half2*)&uN)[1] = __floats2half2_rn(wn * h.z, wn * h.w);
    ((uint2*)g_u1p)[n * 16 + q] = uP;
    ((uint2*)g_u1n)[n * 16 + q] = uN;
    if (q == 0) g_cntpos[n] = 0;
    if (gid == 0) g_cnt3[3 * NN] = 0;
}

// ---------------- E2 layer1: fp16 aggregate (unroll 4) + bias + relu + fused h2 GEMM ----------------
__global__ void k_e2_64(const float* __restrict__ b1, const float* __restrict__ W2) {
    __shared__ float Wt[64 * 16];   // Wt[k*16+c] = W2[c*64+k]
    __shared__ float so[8][64];
    int t = threadIdx.x;
    for (int i = t; i < 1024; i += 256) {
        int c = i >> 6, k = i & 63;
        Wt[k * 16 + c] = W2[i];
    }
    __syncthreads();
    int w = t >> 5, lane = t & 31;
    int wid = blockIdx.x * 8 + w;
    if (wid >= NN) return;
    int g = lane >> 3, l8 = lane & 7;
    int beg = g_rowbeg[wid], cnt = g_indeg[wid];
    const uint4* up = (const uint4*)g_u1p;
    const uint4* un = (const uint4*)g_u1n;
    float acc[8] = {0.f, 0.f, 0.f, 0.f, 0.f, 0.f, 0.f, 0.f};
    int i = g;
    for (; i + 12 < cnt; i += 16) {
        int idx[4], s[4];
        uint4 v[4];
#pragma unroll
        for (int j = 0; j < 4; j++) { idx[j] = beg + i + j * 4; s[j] = g_srt[idx[j]]; }
#pragma unroll
        for (int j = 0; j < 4; j++) {
            unsigned char sg = g_sign[idx[j]];
            v[j] = (sg ? up : un)[s[j] * 8 + l8];
        }
#pragma unroll
        for (int j = 0; j < 4; j++) {
            half2* hp = (half2*)&v[j];
#pragma unroll
            for (int q = 0; q < 4; q++) {
                float2 f = __half22float2(hp[q]);
                acc[2 * q]     += f.x;
                acc[2 * q + 1] += f.y;
            }
        }
    }
    for (; i < cnt; i += 4) {
        int idx = beg + i;
        int s = g_srt[idx];
        uint4 v = (g_sign[idx] ? up : un)[s * 8 + l8];
        half2* hp = (half2*)&v;
#pragma unroll
        for (int q = 0; q < 4; q++) {
            float2 f = __half22float2(hp[q]);
            acc[2 * q]     += f.x;
            acc[2 * q + 1] += f.y;
        }
    }
    if (g == 0) {  // self loop term
        uint4 v = (g_normsq[wid] > 0.f ? up : un)[wid * 8 + l8];
        half2* hp = (half2*)&v;
#pragma unroll
        for (int q = 0; q < 4; q++) {
            float2 f = __half22float2(hp[q]);
            acc[2 * q]     += f.x;
            acc[2 * q + 1] += f.y;
        }
    }
#pragma unroll
    for (int j = 0; j < 8; j++) {
        acc[j] += __shfl_xor_sync(0xffffffffu, acc[j], 8);
        acc[j] += __shfl_xor_sync(0xffffffffu, acc[j], 16);
    }
    if (g == 0) {
#pragma unroll
        for (int j = 0; j < 8; j++)
            so[w][l8 * 8 + j] = fmaxf(acc[j] + b1[l8 * 8 + j], 0.f);
    }
    __syncwarp();
    float acc2 = 0.f;
    int c = lane & 15;
    int k0 = (lane >> 4) * 32;
#pragma unroll
    for (int k = 0; k < 32; k++) acc2 += so[w][k0 + k] * Wt[(k0 + k) * 16 + c];
    acc2 += __shfl_xor_sync(0xffffffffu, acc2, 16);
    float nb = __shfl_down_sync(0xffffffffu, acc2, 1);
    if (lane < 16) {
        g_h2[wid * 16 + lane] = acc2;
        if (!(lane & 1)) {
            half2 hh = __floats2half2_rn(acc2, nb);
            g_h2b[wid * 8 + (lane >> 1)] = *(unsigned int*)&hh;
        }
    }
}

// ---------------- E1 layer2: signs + pos counts (fp16 gathers, unroll 2) ----------------
__global__ void k_e1_16() {
    int wid = (blockIdx.x * blockDim.x + threadIdx.x) >> 5;
    if (wid >= NN) return;
    int lane = threadIdx.x & 31;
    int g = lane >> 2, l4 = lane & 3;
    const float4* h2v = (const float4*)g_h2;
    float4 d = h2v[wid * 4 + l4];
    float nq = d.x * d.x + d.y * d.y + d.z * d.z + d.w * d.w;
    nq += __shfl_xor_sync(0xffffffffu, nq, 1);
    nq += __shfl_xor_sync(0xffffffffu, nq, 2);
    if (lane == 0) g_normsq[wid] = nq;
    int beg = g_rowbeg[wid], cnt = g_indeg[wid];
    unsigned gm = 0xFu << (g * 4);
    const uint2* h2bv = (const uint2*)g_h2b;
    int i = g;
    for (; i + 8 < cnt; i += 16) {
        int idx0 = beg + i, idx1 = beg + i + 8;
        int s0 = g_srt[idx0];
        int s1 = g_srt[idx1];
        uint2 sv0 = h2bv[s0 * 4 + l4];
        uint2 sv1 = h2bv[s1 * 4 + l4];
        float2 p0 = __half22float2(*(half2*)&sv0.x);
        float2 p1 = __half22float2(*(half2*)&sv0.y);
        float2 q0 = __half22float2(*(half2*)&sv1.x);
        float2 q1 = __half22float2(*(half2*)&sv1.y);
        float a0 = d.x * p0.x + d.y * p0.y + d.z * p1.x + d.w * p1.y;
        float a1 = d.x * q0.x + d.y * q0.y + d.z * q1.x + d.w * q1.y;
        a0 += __shfl_xor_sync(gm, a0, 1);
        a1 += __shfl_xor_sync(gm, a1, 1);
        a0 += __shfl_xor_sync(gm, a0, 2);
        a1 += __shfl_xor_sync(gm, a1, 2);
        if (l4 == 0) {
            bool sg0 = a0 > 0.f, sg1 = a1 > 0.f;
            g_sign[idx0] = (unsigned char)sg0;
            g_sign[idx1] = (unsigned char)sg1;
            if (sg0) atomicAdd(&g_cntpos[s0], 1);
            if (sg1) atomicAdd(&g_cntpos[s1], 1);
        }
    }
    if (i < cnt) {
        int idx = beg + i;
        int s = g_srt[idx];
        uint2 sv = h2bv[s * 4 + l4];
        float2 f0 = __half22float2(*(half2*)&sv.x);
        float2 f1 = __half22float2(*(half2*)&sv.y);
        float a = d.x * f0.x + d.y * f0.y + d.z * f1.x + d.w * f1.y;
        a += __shfl_xor_sync(gm, a, 1);
        a += __shfl_xor_sync(gm, a, 2);
        if (l4 == 0) {
            bool sg = a > 0.f;
            g_sign[idx] = (unsigned char)sg;
            if (sg) atomicAdd(&g_cntpos[s], 1);
        }
    }
}

// ---------------- U2: weights + fp16 message tables (layer 2); resets outdeg+cntpos ----------------
__global__ void k_u2() {
    int gid = blockIdx.x * blockDim.x + threadIdx.x;
    if (gid >= NN * 4) return;
    int n = gid >> 2, q = gid & 3;
    bool sp = g_normsq[n] > 0.f;
    int p = g_cntpos[n] + (sp ? 1 : 0);
    int tot = g_outdeg[n] + 1;
    const float E1c = 2.718281828459045f;
    const float EIc = 0.36787944117144233f;
    float denom = (float)p * E1c + (float)(tot - p) * EIc;
    float r = __frcp_rn(denom);
    float wp = E1c * r, wn = EIc * r;
    float4 h = ((const float4*)g_h2)[n * 4 + q];
    uint2 uP, uN;
    ((half2*)&uP)[0] = __floats2half2_rn(wp * h.x, wp * h.y);
    ((half2*)&uP)[1] = __floats2half2_rn(wp * h.z, wp * h.w);
    ((half2*)&uN)[0] = __floats2half2_rn(wn * h.x, wn * h.y);
    ((half2*)&uN)[1] = __floats2half2_rn(wn * h.z, wn * h.w);
    ((uint2*)g_u2p)[n * 4 + q] = uP;
    ((uint2*)g_u2n)[n * 4 + q] = uN;
    if (q == 0) { g_cntpos[n] = 0; g_outdeg[n] = 0; }
}

// ---------------- E2 layer2: fp16 aggregate + bias + log_softmax; resets indeg ----------------
__global__ void k_e2_16(const float* __restrict__ b2, float* __restrict__ out) {
    int wid = (blockIdx.x * blockDim.x + threadIdx.x) >> 5;
    if (wid >= NN) return;
    int lane = threadIdx.x & 31;
    int g = lane >> 2, l4 = lane & 3;
    int beg = g_rowbeg[wid], cnt = g_indeg[wid];
    const uint2* up = (const uint2*)g_u2p;
    const uint2* un = (const uint2*)g_u2n;
    float4 acc = {0.f, 0.f, 0.f, 0.f};
    int i = g;
    for (; i + 8 < cnt; i += 16) {
        int idx0 = beg + i, idx1 = beg + i + 8;
        int s0 = g_srt[idx0];
        int s1 = g_srt[idx1];
        unsigned char sg0 = g_sign[idx0], sg1 = g_sign[idx1];
        uint2 v0 = (sg0 ? up : un)[s0 * 4 + l4];
        uint2 v1 = (sg1 ? up : un)[s1 * 4 + l4];
        float2 p0 = __half22float2(*(half2*)&v0.x);
        float2 p1 = __half22float2(*(half2*)&v0.y);
        float2 q0 = __half22float2(*(half2*)&v1.x);
        float2 q1 = __half22float2(*(half2*)&v1.y);
        acc.x += p0.x + q0.x; acc.y += p0.y + q0.y;
        acc.z += p1.x + q1.x; acc.w += p1.y + q1.y;
    }
    if (i < cnt) {
        int idx = beg + i;
        int s = g_srt[idx];
        uint2 v = (g_sign[idx] ? up : un)[s * 4 + l4];
        float2 f0 = __half22float2(*(half2*)&v.x);
        float2 f1 = __half22float2(*(half2*)&v.y);
        acc.x += f0.x; acc.y += f0.y; acc.z += f1.x; acc.w += f1.y;
    }
    if (g == 0) {  // self
        uint2 v = (g_normsq[wid] > 0.f ? up : un)[wid * 4 + l4];
        float2 f0 = __half22float2(*(half2*)&v.x);
        float2 f1 = __half22float2(*(half2*)&v.y);
        acc.x += f0.x; acc.y += f0.y; acc.z += f1.x; acc.w += f1.y;
    }
#pragma unroll
    for (int o = 4; o < 32; o <<= 1) {
        acc.x += __shfl_xor_sync(0xffffffffu, acc.x, o);
        acc.y += __shfl_xor_sync(0xffffffffu, acc.y, o);
        acc.z += __shfl_xor_sync(0xffffffffu, acc.z, o);
        acc.w += __shfl_xor_sync(0xffffffffu, acc.w, o);
    }
    float4 bb = ((const float4*)b2)[l4];
    float4 v;
    v.x = acc.x + bb.x;
    v.y = acc.y + bb.y;
    v.z = acc.z + bb.z;
    v.w = acc.w + bb.w;
    float m = fmaxf(fmaxf(v.x, v.y), fmaxf(v.z, v.w));
    m = fmaxf(m, __shfl_xor_sync(0xffffffffu, m, 1));
    m = fmaxf(m, __shfl_xor_sync(0xffffffffu, m, 2));
    float e = expf(v.x - m) + expf(v.y - m) + expf(v.z - m) + expf(v.w - m);
    e += __shfl_xor_sync(0xffffffffu, e, 1);
    e += __shfl_xor_sync(0xffffffffu, e, 2);
    float ls = m + logf(e);
    if (lane < 4) {
        float4 rr;
        rr.x = v.x - ls; rr.y = v.y - ls; rr.z = v.z - ls; rr.w = v.w - ls;
        *(float4*)&out[wid * 16 + l4 * 4] = rr;
    }
    if (lane == 0) g_indeg[wid] = 0;  // reset for next call
}

// ---------------- launch ----------------
extern "C" void kernel_launch(void* const* d_in, const int* in_sizes, int n_in,
                              void* d_out, int out_size) {
    (void)in_sizes; (void)n_in; (void)out_size;
    const float* x  = (const float*)d_in[0];
    const int*   ei = (const int*)d_in[1];
    const float* W1 = (const float*)d_in[2];
    const float* b1 = (const float*)d_in[3];
    const float* W2 = (const float*)d_in[4];
    const float* b2 = (const float*)d_in[5];
    float* out = (float*)d_out;

    k_prep<<<SCAT_BLOCKS, 256>>>(ei);
    k_alloc<<<(NN + 255) / 256, 256>>>();
    k_gs<<<GEMM_BLOCKS + SCAT_BLOCKS, 256>>>(x, W1, ei);
    k_e1_64<<<(NN + 7) / 8, 256>>>();          // 4th launch -> profiled
    k_u1<<<(NN * 16 + 255) / 256, 256>>>();
    k_e2_64<<<(NN + 7) / 8, 256>>>(b1, W2);
    k_e1_16<<<(NN + 7) / 8, 256>>>();
    k_u2<<<(NN * 4 + 255) / 256, 256>>>();
    k_e2_16<<<(NN + 7) / 8, 256>>>(b2, out);
}

// round 10
// speedup vs baseline: 1.1051x; 1.0114x over previous
#include <cuda_runtime.h>
#include <cuda_fp16.h>

#define NN 100000
#define NE 1600000
#define GEMM_BLOCKS ((NN + 127) / 128)          // 782
#define SCAT_BLOCKS ((NE / 4 + 255) / 256)      // 1563

// ---------------- device scratch (zero-initialized at load; kernels restore zeros each call) ----------------
__device__ int g_srt[NE];
__device__ unsigned char g_sign[NE];
__device__ int g_cnt3[3 * NN + 1];   // [0,NN)=indeg  [NN,2NN)=outdeg  [2NN,3NN)=cntpos  [3NN]=ctr
__device__ int g_rowbeg[NN];
__device__ int g_wptr[NN];
__device__ float g_normsq[NN];
__device__ uint4 g_h1b[NN * 8];          // fp16 h1, 128B/row
__device__ unsigned int g_h2b[NN * 8];   // fp16 h2, 32B/row
__device__ unsigned int g_wh1[NN];       // half2 (wpos, wneg) layer 1
__device__ unsigned int g_wh2[NN];       // half2 (wpos, wneg) layer 2

#define g_indeg  (g_cnt3)
#define g_outdeg (g_cnt3 + NN)
#define g_cntpos (g_cnt3 + 2 * NN)

// ---------------- prep: indeg only, 4 edges/thread ----------------
__global__ void k_prep(const int* __restrict__ ei) {
    int t = blockIdx.x * blockDim.x + threadIdx.x;
    int e0 = t * 4;
    if (e0 >= NE) return;
    int4 d = *(const int4*)&ei[NE + e0];
    atomicAdd(&g_indeg[d.x], 1);
    atomicAdd(&g_indeg[d.y], 1);
    atomicAdd(&g_indeg[d.z], 1);
    atomicAdd(&g_indeg[d.w], 1);
}

// ---------------- CSR offsets via block-aggregated atomic ----------------
__global__ void k_alloc() {
    __shared__ int warpsum[8];
    __shared__ int sbase;
    int i = blockIdx.x * 256 + threadIdx.x;
    int v = (i < NN) ? g_indeg[i] : 0;
    int lane = threadIdx.x & 31, w = threadIdx.x >> 5;
    int incl = v;
#pragma unroll
    for (int o = 1; o < 32; o <<= 1) {
        int u = __shfl_up_sync(0xffffffffu, incl, o);
        if (lane >= o) incl += u;
    }
    if (lane == 31) warpsum[w] = incl;
    __syncthreads();
    if (w == 0) {
        int s = (lane < 8) ? warpsum[lane] : 0;
#pragma unroll
        for (int o = 1; o < 8; o <<= 1) {
            int u = __shfl_up_sync(0xffffffffu, s, o);
            if (lane >= o) s += u;
        }
        if (lane < 8) warpsum[lane] = s;
        if (lane == 7) sbase = atomicAdd(&g_cnt3[3 * NN], s);
    }
    __syncthreads();
    int excl = incl - v + (w ? warpsum[w - 1] : 0);
    if (i < NN) {
        int r = sbase + excl;
        g_rowbeg[i] = r;
        g_wptr[i] = r;
    }
}

// ---------------- merged: GEMM blocks [0,782) + scatter/outdeg blocks ----------------
__global__ void __launch_bounds__(256) k_gs(const float* __restrict__ x, const float* __restrict__ W,
                                            const int* __restrict__ ei) {
    __shared__ float Ws[64 * 64];       // Ws[k*64+c] = W[c*64+k]
    __shared__ float sx[128 * 68];
    int t = threadIdx.x;
    if (blockIdx.x >= GEMM_BLOCKS) {
        int b = blockIdx.x - GEMM_BLOCKS;
        int e0 = (b * 256 + t) * 4;
        if (e0 >= NE) return;
        int4 s = *(const int4*)&ei[e0];
        int4 d = *(const int4*)&ei[NE + e0];
        atomicAdd(&g_outdeg[s.x], 1);
        atomicAdd(&g_outdeg[s.y], 1);
        atomicAdd(&g_outdeg[s.z], 1);
        atomicAdd(&g_outdeg[s.w], 1);
        int p0 = atomicAdd(&g_wptr[d.x], 1);
        int p1 = atomicAdd(&g_wptr[d.y], 1);
        int p2 = atomicAdd(&g_wptr[d.z], 1);
        int p3 = atomicAdd(&g_wptr[d.w], 1);
        g_srt[p0] = s.x;
        g_srt[p1] = s.y;
        g_srt[p2] = s.z;
        g_srt[p3] = s.w;
        return;
    }
    for (int i = t; i < 4096; i += 256) {
        int c = i >> 6, k = i & 63;
        Ws[k * 64 + c] = W[i];
    }
    int r0 = blockIdx.x * 128;
    int nrows = NN - r0; if (nrows > 128) nrows = 128;
    for (int i = t; i < nrows * 16; i += 256) {
        int row = i >> 4, cc = i & 15;
        float4 v = ((const float4*)x)[(r0 + row) * 16 + cc];
        *(float4*)&sx[row * 68 + cc * 4] = v;
    }
    __syncthreads();
    int tc = t & 7;
    int tr = t >> 3;
    int rbase = tr * 4;
    float a[4][8];
#pragma unroll
    for (int r = 0; r < 4; r++)
#pragma unroll
        for (int c = 0; c < 8; c++) a[r][c] = 0.f;
#pragma unroll
    for (int k = 0; k < 64; k += 4) {
        float4 xr[4];
#pragma unroll
        for (int r = 0; r < 4; r++) xr[r] = *(const float4*)&sx[(rbase + r) * 68 + k];
#pragma unroll
        for (int kk = 0; kk < 4; kk++) {
            float4 w0 = *(const float4*)&Ws[(k + kk) * 64 + tc * 8];
            float4 w1 = *(const float4*)&Ws[(k + kk) * 64 + tc * 8 + 4];
#pragma unroll
            for (int r = 0; r < 4; r++) {
                float xv = (kk == 0) ? xr[r].x : (kk == 1) ? xr[r].y : (kk == 2) ? xr[r].z : xr[r].w;
                a[r][0] += xv * w0.x; a[r][1] += xv * w0.y;
                a[r][2] += xv * w0.z; a[r][3] += xv * w0.w;
                a[r][4] += xv * w1.x; a[r][5] += xv * w1.y;
                a[r][6] += xv * w1.z; a[r][7] += xv * w1.w;
            }
        }
    }
#pragma unroll
    for (int r = 0; r < 4; r++) {
        int row = r0 + rbase + r;
        if (rbase + r < nrows) {
            uint4 hb;
            ((half2*)&hb)[0] = __floats2half2_rn(a[r][0], a[r][1]);
            ((half2*)&hb)[1] = __floats2half2_rn(a[r][2], a[r][3]);
            ((half2*)&hb)[2] = __floats2half2_rn(a[r][4], a[r][5]);
            ((half2*)&hb)[3] = __floats2half2_rn(a[r][6], a[r][7]);
            g_h1b[row * 8 + tc] = hb;
        }
    }
}

// ---------------- helpers ----------------
__device__ __forceinline__ float dot8h(float4 d0, float4 d1, uint4 v) {
    float2 f0 = __half22float2(((half2*)&v)[0]);
    float2 f1 = __half22float2(((half2*)&v)[1]);
    float2 f2 = __half22float2(((half2*)&v)[2]);
    float2 f3 = __half22float2(((half2*)&v)[3]);
    return d0.x * f0.x + d0.y * f0.y + d0.z * f1.x + d0.w * f1.y
         + d1.x * f2.x + d1.y * f2.y + d1.z * f3.x + d1.w * f3.y;
}

// ---------------- E1 layer1: signs + pos counts (fp16 everywhere) ----------------
__global__ void k_e1_64() {
    int wid = (blockIdx.x * blockDim.x + threadIdx.x) >> 5;
    if (wid >= NN) return;
    int lane = threadIdx.x & 31;
    int g = lane >> 3, l8 = lane & 7;
    uint4 dv = g_h1b[wid * 8 + l8];
    float2 e0 = __half22float2(((half2*)&dv)[0]);
    float2 e1 = __half22float2(((half2*)&dv)[1]);
    float2 e2 = __half22float2(((half2*)&dv)[2]);
    float2 e3 = __half22float2(((half2*)&dv)[3]);
    float4 d0 = {e0.x, e0.y, e1.x, e1.y};
    float4 d1 = {e2.x, e2.y, e3.x, e3.y};
    float nq = d0.x * d0.x + d0.y * d0.y + d0.z * d0.z + d0.w * d0.w
             + d1.x * d1.x + d1.y * d1.y + d1.z * d1.z + d1.w * d1.w;
    unsigned gm = 0xFFu << (g * 8);
    nq += __shfl_xor_sync(0xffffffffu, nq, 1);
    nq += __shfl_xor_sync(0xffffffffu, nq, 2);
    nq += __shfl_xor_sync(0xffffffffu, nq, 4);
    if (lane == 0) g_normsq[wid] = nq;
    int beg = g_rowbeg[wid], cnt = g_indeg[wid];
    int i = g;
    for (; i + 12 < cnt; i += 16) {
        int idx[4], s[4];
        uint4 v[4];
        float a[4];
#pragma unroll
        for (int j = 0; j < 4; j++) { idx[j] = beg + i + j * 4; s[j] = g_srt[idx[j]]; }
#pragma unroll
        for (int j = 0; j < 4; j++) v[j] = g_h1b[s[j] * 8 + l8];
#pragma unroll
        for (int j = 0; j < 4; j++) a[j] = dot8h(d0, d1, v[j]);
#pragma unroll
        for (int o = 1; o <= 4; o <<= 1)
#pragma unroll
            for (int j = 0; j < 4; j++) a[j] += __shfl_xor_sync(gm, a[j], o);
        if (l8 == 0) {
#pragma unroll
            for (int j = 0; j < 4; j++) {
                bool sg = a[j] > 0.f;
                g_sign[idx[j]] = (unsigned char)sg;
                if (sg) atomicAdd(&g_cntpos[s[j]], 1);
            }
        }
    }
    for (; i < cnt; i += 4) {
        int idx = beg + i;
        int s = g_srt[idx];
        uint4 v = g_h1b[s * 8 + l8];
        float a = dot8h(d0, d1, v);
        a += __shfl_xor_sync(gm, a, 1);
        a += __shfl_xor_sync(gm, a, 2);
        a += __shfl_xor_sync(gm, a, 4);
        if (l8 == 0) {
            bool sg = a > 0.f;
            g_sign[idx] = (unsigned char)sg;
            if (sg) atomicAdd(&g_cntpos[s], 1);
        }
    }
}

// ---------------- W1: per-node weight pair; resets cntpos + ctr ----------------
__global__ void k_w1() {
    int n = blockIdx.x * blockDim.x + threadIdx.x;
    if (n >= NN) return;
    bool sp = g_normsq[n] > 0.f;
    int p = g_cntpos[n] + (sp ? 1 : 0);
    int tot = g_outdeg[n] + 1;
    const float E1c = 2.718281828459045f;
    const float EIc = 0.36787944117144233f;
    float denom = (float)p * E1c + (float)(tot - p) * EIc;
    float r = __frcp_rn(denom);
    half2 wh = __floats2half2_rn(E1c * r, EIc * r);
    g_wh1[n] = *(unsigned int*)&wh;
    g_cntpos[n] = 0;
    if (n == 0) g_cnt3[3 * NN] = 0;
}

// ---------------- E2 layer1: weighted fp16 aggregate + bias + relu + fused h2 GEMM ----------------
__global__ void k_e2_64(const float* __restrict__ b1, const float* __restrict__ W2) {
    __shared__ float Wt[64 * 16];   // Wt[k*16+c] = W2[c*64+k]
    __shared__ float so[8][64];
    int t = threadIdx.x;
    for (int i = t; i < 1024; i += 256) {
        int c = i >> 6, k = i & 63;
        Wt[k * 16 + c] = W2[i];
    }
    __syncthreads();
    int w = t >> 5, lane = t & 31;
    int wid = blockIdx.x * 8 + w;
    if (wid >= NN) return;
    int g = lane >> 3, l8 = lane & 7;
    int beg = g_rowbeg[wid], cnt = g_indeg[wid];
    float acc[8] = {0.f, 0.f, 0.f, 0.f, 0.f, 0.f, 0.f, 0.f};
    int i = g;
    for (; i + 12 < cnt; i += 16) {
        int idx[4], s[4];
        uint4 v[4];
        float wgt[4];
#pragma unroll
        for (int j = 0; j < 4; j++) { idx[j] = beg + i + j * 4; s[j] = g_srt[idx[j]]; }
#pragma unroll
        for (int j = 0; j < 4; j++) {
            unsigned char sg = g_sign[idx[j]];
            unsigned int whb = g_wh1[s[j]];
            float2 wf = __half22float2(*(half2*)&whb);
            wgt[j] = sg ? wf.x : wf.y;
            v[j] = g_h1b[s[j] * 8 + l8];
        }
#pragma unroll
        for (int j = 0; j < 4; j++) {
            half2* hp = (half2*)&v[j];
#pragma unroll
            for (int q = 0; q < 4; q++) {
                float2 f = __half22float2(hp[q]);
                acc[2 * q]     += wgt[j] * f.x;
                acc[2 * q + 1] += wgt[j] * f.y;
            }
        }
    }
    for (; i < cnt; i += 4) {
        int idx = beg + i;
        int s = g_srt[idx];
        unsigned char sg = g_sign[idx];
        unsigned int whb = g_wh1[s];
        float2 wf = __half22float2(*(half2*)&whb);
        float wgt = sg ? wf.x : wf.y;
        uint4 v = g_h1b[s * 8 + l8];
        half2* hp = (half2*)&v;
#pragma unroll
        for (int q = 0; q < 4; q++) {
            float2 f = __half22float2(hp[q]);
            acc[2 * q]     += wgt * f.x;
            acc[2 * q + 1] += wgt * f.y;
        }
    }
    if (g == 0) {  // self loop term
        unsigned int whb = g_wh1[wid];
        float2 wf = __half22float2(*(half2*)&whb);
        float wgt = (g_normsq[wid] > 0.f) ? wf.x : wf.y;
        uint4 v = g_h1b[wid * 8 + l8];
        half2* hp = (half2*)&v;
#pragma unroll
        for (int q = 0; q < 4; q++) {
            float2 f = __half22float2(hp[q]);
            acc[2 * q]     += wgt * f.x;
            acc[2 * q + 1] += wgt * f.y;
        }
    }
#pragma unroll
    for (int j = 0; j < 8; j++) {
        acc[j] += __shfl_xor_sync(0xffffffffu, acc[j], 8);
        acc[j] += __shfl_xor_sync(0xffffffffu, acc[j], 16);
    }
    if (g == 0) {
#pragma unroll
        for (int j = 0; j < 8; j++)
            so[w][l8 * 8 + j] = fmaxf(acc[j] + b1[l8 * 8 + j], 0.f);
    }
    __syncwarp();
    // fused h2 = o @ W2^T (16 outputs, k split by half-warp)
    float acc2 = 0.f;
    int c = lane & 15;
    int k0 = (lane >> 4) * 32;
#pragma unroll
    for (int k = 0; k < 32; k++) acc2 += so[w][k0 + k] * Wt[(k0 + k) * 16 + c];
    acc2 += __shfl_xor_sync(0xffffffffu, acc2, 16);
    float nb = __shfl_down_sync(0xffffffffu, acc2, 1);
    if (lane < 16 && !(lane & 1)) {
        half2 hh = __floats2half2_rn(acc2, nb);
        g_h2b[wid * 8 + (lane >> 1)] = *(unsigned int*)&hh;
    }
}

// ---------------- E1 layer2: signs + pos counts (fp16) ----------------
__global__ void k_e1_16() {
    int wid = (blockIdx.x * blockDim.x + threadIdx.x) >> 5;
    if (wid >= NN) return;
    int lane = threadIdx.x & 31;
    int g = lane >> 2, l4 = lane & 3;
    const uint2* h2bv = (const uint2*)g_h2b;
    uint2 dvv = h2bv[wid * 4 + l4];
    float2 e0 = __half22float2(*(half2*)&dvv.x);
    float2 e1 = __half22float2(*(half2*)&dvv.y);
    float4 d = {e0.x, e0.y, e1.x, e1.y};
    float nq = d.x * d.x + d.y * d.y + d.z * d.z + d.w * d.w;
    nq += __shfl_xor_sync(0xffffffffu, nq, 1);
    nq += __shfl_xor_sync(0xffffffffu, nq, 2);
    if (lane == 0) g_normsq[wid] = nq;
    int beg = g_rowbeg[wid], cnt = g_indeg[wid];
    unsigned gm = 0xFu << (g * 4);
    int i = g;
    for (; i + 8 < cnt; i += 16) {
        int idx0 = beg + i, idx1 = beg + i + 8;
        int s0 = g_srt[idx0];
        int s1 = g_srt[idx1];
        uint2 sv0 = h2bv[s0 * 4 + l4];
        uint2 sv1 = h2bv[s1 * 4 + l4];
        float2 p0 = __half22float2(*(half2*)&sv0.x);
        float2 p1 = __half22float2(*(half2*)&sv0.y);
        float2 q0 = __half22float2(*(half2*)&sv1.x);
        float2 q1 = __half22float2(*(half2*)&sv1.y);
        float a0 = d.x * p0.x + d.y * p0.y + d.z * p1.x + d.w * p1.y;
        float a1 = d.x * q0.x + d.y * q0.y + d.z * q1.x + d.w * q1.y;
        a0 += __shfl_xor_sync(gm, a0, 1);
        a1 += __shfl_xor_sync(gm, a1, 1);
        a0 += __shfl_xor_sync(gm, a0, 2);
        a1 += __shfl_xor_sync(gm, a1, 2);
        if (l4 == 0) {
            bool sg0 = a0 > 0.f, sg1 = a1 > 0.f;
            g_sign[idx0] = (unsigned char)sg0;
            g_sign[idx1] = (unsigned char)sg1;
            if (sg0) atomicAdd(&g_cntpos[s0], 1);
            if (sg1) atomicAdd(&g_cntpos[s1], 1);
        }
    }
    if (i < cnt) {
        int idx = beg + i;
        int s = g_srt[idx];
        uint2 sv = h2bv[s * 4 + l4];
        float2 f0 = __half22float2(*(half2*)&sv.x);
        float2 f1 = __half22float2(*(half2*)&sv.y);
        float a = d.x * f0.x + d.y * f0.y + d.z * f1.x + d.w * f1.y;
        a += __shfl_xor_sync(gm, a, 1);
        a += __shfl_xor_sync(gm, a, 2);
        if (l4 == 0) {
            bool sg = a > 0.f;
            g_sign[idx] = (unsigned char)sg;
            if (sg) atomicAdd(&g_cntpos[s], 1);
        }
    }
}

// ---------------- W2: per-node weight pair; resets cntpos + outdeg ----------------
__global__ void k_w2() {
    int n = blockIdx.x * blockDim.x + threadIdx.x;
    if (n >= NN) return;
    bool sp = g_normsq[n] > 0.f;
    int p = g_cntpos[n] + (sp ? 1 : 0);
    int tot = g_outdeg[n] + 1;
    const float E1c = 2.718281828459045f;
    const float EIc = 0.36787944117144233f;
    float denom = (float)p * E1c + (float)(tot - p) * EIc;
    float r = __frcp_rn(denom);
    half2 wh = __floats2half2_rn(E1c * r, EIc * r);
    g_wh2[n] = *(unsigned int*)&wh;
    g_cntpos[n] = 0;
    g_outdeg[n] = 0;
}

// ---------------- E2 layer2: weighted fp16 aggregate + bias + log_softmax; resets indeg ----------------
__global__ void k_e2_16(const float* __restrict__ b2, float* __restrict__ out) {
    int wid = (blockIdx.x * blockDim.x + threadIdx.x) >> 5;
    if (wid >= NN) return;
    int lane = threadIdx.x & 31;
    int g = lane >> 2, l4 = lane & 3;
    int beg = g_rowbeg[wid], cnt = g_indeg[wid];
    const uint2* h2bv = (const uint2*)g_h2b;
    float4 acc = {0.f, 0.f, 0.f, 0.f};
    int i = g;
    for (; i + 8 < cnt; i += 16) {
        int idx0 = beg + i, idx1 = beg + i + 8;
        int s0 = g_srt[idx0];
        int s1 = g_srt[idx1];
        unsigned char sg0 = g_sign[idx0], sg1 = g_sign[idx1];
        unsigned int wb0 = g_wh2[s0], wb1 = g_wh2[s1];
        float2 wf0 = __half22float2(*(half2*)&wb0);
        float2 wf1 = __half22float2(*(half2*)&wb1);
        float w0 = sg0 ? wf0.x : wf0.y;
        float w1 = sg1 ? wf1.x : wf1.y;
        uint2 v0 = h2bv[s0 * 4 + l4];
        uint2 v1 = h2bv[s1 * 4 + l4];
        float2 p0 = __half22float2(*(half2*)&v0.x);
        float2 p1 = __half22float2(*(half2*)&v0.y);
        float2 q0 = __half22float2(*(half2*)&v1.x);
        float2 q1 = __half22float2(*(half2*)&v1.y);
        acc.x += w0 * p0.x + w1 * q0.x;
        acc.y += w0 * p0.y + w1 * q0.y;
        acc.z += w0 * p1.x + w1 * q1.x;
        acc.w += w0 * p1.y + w1 * q1.y;
    }
    if (i < cnt) {
        int idx = beg + i;
        int s = g_srt[idx];
        unsigned char sg = g_sign[idx];
        unsigned int wb = g_wh2[s];
        float2 wf = __half22float2(*(half2*)&wb);
        float w = sg ? wf.x : wf.y;
        uint2 v = h2bv[s * 4 + l4];
        float2 f0 = __half22float2(*(half2*)&v.x);
        float2 f1 = __half22float2(*(half2*)&v.y);
        acc.x += w * f0.x; acc.y += w * f0.y;
        acc.z += w * f1.x; acc.w += w * f1.y;
    }
    if (g == 0) {  // self
        unsigned int wb = g_wh2[wid];
        float2 wf = __half22float2(*(half2*)&wb);
        float w = (g_normsq[wid] > 0.f) ? wf.x : wf.y;
        uint2 v = h2bv[wid * 4 + l4];
        float2 f0 = __half22float2(*(half2*)&v.x);
        float2 f1 = __half22float2(*(half2*)&v.y);
        acc.x += w * f0.x; acc.y += w * f0.y;
        acc.z += w * f1.x; acc.w += w * f1.y;
    }
#pragma unroll
    for (int o = 4; o < 32; o <<= 1) {
        acc.x += __shfl_xor_sync(0xffffffffu, acc.x, o);
        acc.y += __shfl_xor_sync(0xffffffffu, acc.y, o);
        acc.z += __shfl_xor_sync(0xffffffffu, acc.z, o);
        acc.w += __shfl_xor_sync(0xffffffffu, acc.w, o);
    }
    float4 bb = ((const float4*)b2)[l4];
    float4 v;
    v.x = acc.x + bb.x;
    v.y = acc.y + bb.y;
    v.z = acc.z + bb.z;
    v.w = acc.w + bb.w;
    float m = fmaxf(fmaxf(v.x, v.y), fmaxf(v.z, v.w));
    m = fmaxf(m, __shfl_xor_sync(0xffffffffu, m, 1));
    m = fmaxf(m, __shfl_xor_sync(0xffffffffu, m, 2));
    float e = expf(v.x - m) + expf(v.y - m) + expf(v.z - m) + expf(v.w - m);
    e += __shfl_xor_sync(0xffffffffu, e, 1);
    e += __shfl_xor_sync(0xffffffffu, e, 2);
    float ls = m + logf(e);
    if (lane < 4) {
        float4 rr;
        rr.x = v.x - ls; rr.y = v.y - ls; rr.z = v.z - ls; rr.w = v.w - ls;
        *(float4*)&out[wid * 16 + l4 * 4] = rr;
    }
    if (lane == 0) g_indeg[wid] = 0;  // reset for next call
}

// ---------------- launch ----------------
extern "C" void kernel_launch(void* const* d_in, const int* in_sizes, int n_in,
                              void* d_out, int out_size) {
    (void)in_sizes; (void)n_in; (void)out_size;
    const float* x  = (const float*)d_in[0];
    const int*   ei = (const int*)d_in[1];
    const float* W1 = (const float*)d_in[2];
    const float* b1 = (const float*)d_in[3];
    const float* W2 = (const float*)d_in[4];
    const float* b2 = (const float*)d_in[5];
    float* out = (float*)d_out;

    k_prep<<<SCAT_BLOCKS, 256>>>(ei);
    k_alloc<<<(NN + 255) / 256, 256>>>();
    k_gs<<<GEMM_BLOCKS + SCAT_BLOCKS, 256>>>(x, W1, ei);
    k_e1_64<<<(NN + 7) / 8, 256>>>();          // 4th launch -> profiled
    k_w1<<<(NN + 255) / 256, 256>>>();
    k_e2_64<<<(NN + 7) / 8, 256>>>(b1, W2);
    k_e1_16<<<(NN + 7) / 8, 256>>>();
    k_w2<<<(NN + 255) / 256, 256>>>();
    k_e2_16<<<(NN + 7) / 8, 256>>>(b2, out);
}

// round 14
// speedup vs baseline: 1.1273x; 1.0201x over previous
#include <cuda_runtime.h>
#include <cuda_fp16.h>

#define NN 100000
#define NE 1600000
#define GEMM_BLOCKS ((NN + 127) / 128)          // 782
#define SCAT_BLOCKS ((NE / 4 + 255) / 256)      // 1563
#define E_H  2.71875f                           // fp16-exact e
#define IE_H 0.367919921875f                    // fp16-exact 1/e

// ---------------- device scratch (zero-initialized at load; kernels restore zeros each call) ----------------
__device__ int g_srt[NE];
__device__ unsigned char g_sign[NE];
__device__ int g_cnt3[3 * NN + 1];   // [0,NN)=indeg  [NN,2NN)=outdeg  [2NN,3NN)=cntpos  [3NN]=ctr
__device__ int g_rowbeg[NN];
__device__ int g_wptr[NN];
__device__ float g_normsq[NN];
__device__ uint4 g_h1b[NN * 8];          // fp16 h1, 128B/row (unscaled)
__device__ uint4 g_h1s[NN * 8];          // fp16 h1/D, 128B/row (scaled)
__device__ unsigned int g_h2b[NN * 8];   // fp16 h2, 32B/row (unscaled)
__device__ unsigned int g_h2s[NN * 8];   // fp16 h2/D, 32B/row (scaled)

#define g_indeg  (g_cnt3)
#define g_outdeg (g_cnt3 + NN)
#define g_cntpos (g_cnt3 + 2 * NN)

// ---------------- prep: indeg only, 4 edges/thread ----------------
__global__ void k_prep(const int* __restrict__ ei) {
    int t = blockIdx.x * blockDim.x + threadIdx.x;
    int e0 = t * 4;
    if (e0 >= NE) return;
    int4 d = *(const int4*)&ei[NE + e0];
    atomicAdd(&g_indeg[d.x], 1);
    atomicAdd(&g_indeg[d.y], 1);
    atomicAdd(&g_indeg[d.z], 1);
    atomicAdd(&g_indeg[d.w], 1);
}

// ---------------- CSR offsets via block-aggregated atomic ----------------
__global__ void k_alloc() {
    __shared__ int warpsum[8];
    __shared__ int sbase;
    int i = blockIdx.x * 256 + threadIdx.x;
    int v = (i < NN) ? g_indeg[i] : 0;
    int lane = threadIdx.x & 31, w = threadIdx.x >> 5;
    int incl = v;
#pragma unroll
    for (int o = 1; o < 32; o <<= 1) {
        int u = __shfl_up_sync(0xffffffffu, incl, o);
        if (lane >= o) incl += u;
    }
    if (lane == 31) warpsum[w] = incl;
    __syncthreads();
    if (w == 0) {
        int s = (lane < 8) ? warpsum[lane] : 0;
#pragma unroll
        for (int o = 1; o < 8; o <<= 1) {
            int u = __shfl_up_sync(0xffffffffu, s, o);
            if (lane >= o) s += u;
        }
        if (lane < 8) warpsum[lane] = s;
        if (lane == 7) sbase = atomicAdd(&g_cnt3[3 * NN], s);
    }
    __syncthreads();
    int excl = incl - v + (w ? warpsum[w - 1] : 0);
    if (i < NN) {
        int r = sbase + excl;
        g_rowbeg[i] = r;
        g_wptr[i] = r;
    }
}

// ---------------- merged: GEMM blocks [0,782) + scatter/outdeg blocks ----------------
__global__ void __launch_bounds__(256) k_gs(const float* __restrict__ x, const float* __restrict__ W,
                                            const int* __restrict__ ei) {
    __shared__ float Ws[64 * 64];
    __shared__ float sx[128 * 68];
    int t = threadIdx.x;
    if (blockIdx.x >= GEMM_BLOCKS) {
        int b = blockIdx.x - GEMM_BLOCKS;
        int e0 = (b * 256 + t) * 4;
        if (e0 >= NE) return;
        int4 s = *(const int4*)&ei[e0];
        int4 d = *(const int4*)&ei[NE + e0];
        atomicAdd(&g_outdeg[s.x], 1);
        atomicAdd(&g_outdeg[s.y], 1);
        atomicAdd(&g_outdeg[s.z], 1);
        atomicAdd(&g_outdeg[s.w], 1);
        int p0 = atomicAdd(&g_wptr[d.x], 1);
        int p1 = atomicAdd(&g_wptr[d.y], 1);
        int p2 = atomicAdd(&g_wptr[d.z], 1);
        int p3 = atomicAdd(&g_wptr[d.w], 1);
        g_srt[p0] = s.x;
        g_srt[p1] = s.y;
        g_srt[p2] = s.z;
        g_srt[p3] = s.w;
        return;
    }
    for (int i = t; i < 4096; i += 256) {
        int c = i >> 6, k = i & 63;
        Ws[k * 64 + c] = W[i];
    }
    int r0 = blockIdx.x * 128;
    int nrows = NN - r0; if (nrows > 128) nrows = 128;
    for (int i = t; i < nrows * 16; i += 256) {
        int row = i >> 4, cc = i & 15;
        float4 v = ((const float4*)x)[(r0 + row) * 16 + cc];
        *(float4*)&sx[row * 68 + cc * 4] = v;
    }
    __syncthreads();
    int tc = t & 7;
    int tr = t >> 3;
    int rbase = tr * 4;
    float a[4][8];
#pragma unroll
    for (int r = 0; r < 4; r++)
#pragma unroll
        for (int c = 0; c < 8; c++) a[r][c] = 0.f;
#pragma unroll
    for (int k = 0; k < 64; k += 4) {
        float4 xr[4];
#pragma unroll
        for (int r = 0; r < 4; r++) xr[r] = *(const float4*)&sx[(rbase + r) * 68 + k];
#pragma unroll
        for (int kk = 0; kk < 4; kk++) {
            float4 w0 = *(const float4*)&Ws[(k + kk) * 64 + tc * 8];
            float4 w1 = *(const float4*)&Ws[(k + kk) * 64 + tc * 8 + 4];
#pragma unroll
            for (int r = 0; r < 4; r++) {
                float xv = (kk == 0) ? xr[r].x : (kk == 1) ? xr[r].y : (kk == 2) ? xr[r].z : xr[r].w;
                a[r][0] += xv * w0.x; a[r][1] += xv * w0.y;
                a[r][2] += xv * w0.z; a[r][3] += xv * w0.w;
                a[r][4] += xv * w1.x; a[r][5] += xv * w1.y;
                a[r][6] += xv * w1.z; a[r][7] += xv * w1.w;
            }
        }
    }
#pragma unroll
    for (int r = 0; r < 4; r++) {
        int row = r0 + rbase + r;
        if (rbase + r < nrows) {
            uint4 hb;
            ((half2*)&hb)[0] = __floats2half2_rn(a[r][0], a[r][1]);
            ((half2*)&hb)[1] = __floats2half2_rn(a[r][2], a[r][3]);
            ((half2*)&hb)[2] = __floats2half2_rn(a[r][4], a[r][5]);
            ((half2*)&hb)[3] = __floats2half2_rn(a[r][6], a[r][7]);
            g_h1b[row * 8 + tc] = hb;
        }
    }
}

// ---------------- helpers: depth-2 fp16 chain dots ----------------
__device__ __forceinline__ float dot8c(half2 d0, half2 d1, half2 d2, half2 d3, uint4 v) {
    half2 c0 = __hfma2(d1, ((const half2*)&v)[1], __hmul2(d0, ((const half2*)&v)[0]));
    half2 c1 = __hfma2(d3, ((const half2*)&v)[3], __hmul2(d2, ((const half2*)&v)[2]));
    float2 f0 = __half22float2(c0), f1 = __half22float2(c1);
    return (f0.x + f0.y) + (f1.x + f1.y);
}
__device__ __forceinline__ float dot4c(half2 d0, half2 d1, uint2 v) {
    half2 c0 = __hfma2(d1, *(const half2*)&v.y, __hmul2(d0, *(const half2*)&v.x));
    float2 f0 = __half22float2(c0);
    return f0.x + f0.y;
}

// ---------------- E1 layer1: signs + pos counts ----------------
__global__ void k_e1_64() {
    int wid = (blockIdx.x * blockDim.x + threadIdx.x) >> 5;
    if (wid >= NN) return;
    int lane = threadIdx.x & 31;
    int g = lane >> 3, l8 = lane & 7;
    uint4 dv = g_h1b[wid * 8 + l8];
    half2 d0 = ((half2*)&dv)[0], d1 = ((half2*)&dv)[1];
    half2 d2 = ((half2*)&dv)[2], d3 = ((half2*)&dv)[3];
    float nq = dot8c(d0, d1, d2, d3, dv);
    nq += __shfl_xor_sync(0xffffffffu, nq, 1);
    nq += __shfl_xor_sync(0xffffffffu, nq, 2);
    nq += __shfl_xor_sync(0xffffffffu, nq, 4);
    if (lane == 0) g_normsq[wid] = nq;
    int beg = g_rowbeg[wid], cnt = g_indeg[wid];
    int i = g;
    for (; i + 12 < cnt; i += 16) {
        int idx[4], s[4];
        uint4 v[4];
        float a[4];
#pragma unroll
        for (int j = 0; j < 4; j++) { idx[j] = beg + i + j * 4; s[j] = g_srt[idx[j]]; }
#pragma unroll
        for (int j = 0; j < 4; j++) v[j] = g_h1b[s[j] * 8 + l8];
#pragma unroll
        for (int j = 0; j < 4; j++) a[j] = dot8c(d0, d1, d2, d3, v[j]);
#pragma unroll
        for (int o = 1; o <= 4; o <<= 1)
#pragma unroll
            for (int j = 0; j < 4; j++) a[j] += __shfl_xor_sync(0xffffffffu, a[j], o);
        if (l8 == 0) {
#pragma unroll
            for (int j = 0; j < 4; j++) {
                bool sg = a[j] > 0.f;
                g_sign[idx[j]] = (unsigned char)sg;
                if (sg) atomicAdd(&g_cntpos[s[j]], 1);
            }
        }
    }
    for (; i < cnt; i += 4) {
        int idx = beg + i;
        int s = g_srt[idx];
        uint4 v = g_h1b[s * 8 + l8];
        float a = dot8c(d0, d1, d2, d3, v);
        a += __shfl_xor_sync(0xffffffffu, a, 1);
        a += __shfl_xor_sync(0xffffffffu, a, 2);
        a += __shfl_xor_sync(0xffffffffu, a, 4);
        if (l8 == 0) {
            bool sg = a > 0.f;
            g_sign[idx] = (unsigned char)sg;
            if (sg) atomicAdd(&g_cntpos[s], 1);
        }
    }
}

// ---------------- W1: scale h1 rows by 1/D; resets cntpos + ctr ----------------
__global__ void k_w1() {
    int gid = blockIdx.x * blockDim.x + threadIdx.x;
    if (gid >= NN * 8) return;
    int n = gid >> 3, q = gid & 7;
    bool sp = g_normsq[n] > 0.f;
    int p = g_cntpos[n] + (sp ? 1 : 0);
    int tot = g_outdeg[n] + 1;
    float denom = (float)p * E_H + (float)(tot - p) * IE_H;
    float r = __frcp_rn(denom);
    uint4 h = g_h1b[n * 8 + q];
    uint4 o;
#pragma unroll
    for (int j = 0; j < 4; j++) {
        float2 f = __half22float2(((half2*)&h)[j]);
        ((half2*)&o)[j] = __floats2half2_rn(r * f.x, r * f.y);
    }
    g_h1s[n * 8 + q] = o;
    if (q == 0) g_cntpos[n] = 0;
    if (gid == 0) g_cnt3[3 * NN] = 0;
}

// ---------------- E2 layer1: aggregate scaled rows + bias + relu + fused h2 GEMM ----------------
__global__ void k_e2_64(const float* __restrict__ b1, const float* __restrict__ W2) {
    __shared__ float Wt[64 * 16];   // Wt[k*16+c] = W2[c*64+k]
    __shared__ float so[8][64];
    int t = threadIdx.x;
    for (int i = t; i < 1024; i += 256) {
        int c = i >> 6, k = i & 63;
        Wt[k * 16 + c] = W2[i];
    }
    __syncthreads();
    int w = t >> 5, lane = t & 31;
    int wid = blockIdx.x * 8 + w;
    if (wid >= NN) return;
    int g = lane >> 3, l8 = lane & 7;
    int beg = g_rowbeg[wid], cnt = g_indeg[wid];
    float acc[8] = {0.f, 0.f, 0.f, 0.f, 0.f, 0.f, 0.f, 0.f};
    int i = g;
    for (; i + 12 < cnt; i += 16) {
        int idx[4], s[4];
        uint4 v[4];
        float cf[4];
#pragma unroll
        for (int j = 0; j < 4; j++) { idx[j] = beg + i + j * 4; s[j] = g_srt[idx[j]]; }
#pragma unroll
        for (int j = 0; j < 4; j++) {
            cf[j] = g_sign[idx[j]] ? E_H : IE_H;
            v[j] = g_h1s[s[j] * 8 + l8];
        }
#pragma unroll
        for (int j = 0; j < 4; j++) {
            half2* hp = (half2*)&v[j];
#pragma unroll
            for (int q = 0; q < 4; q++) {
                float2 f = __half22float2(hp[q]);
                acc[2 * q]     += cf[j] * f.x;
                acc[2 * q + 1] += cf[j] * f.y;
            }
        }
    }
    for (; i < cnt; i += 4) {
        int idx = beg + i;
        int s = g_srt[idx];
        float cf = g_sign[idx] ? E_H : IE_H;
        uint4 v = g_h1s[s * 8 + l8];
        half2* hp = (half2*)&v;
#pragma unroll
        for (int q = 0; q < 4; q++) {
            float2 f = __half22float2(hp[q]);
            acc[2 * q]     += cf * f.x;
            acc[2 * q + 1] += cf * f.y;
        }
    }
    if (g == 0) {  // self loop term
        float cf = (g_normsq[wid] > 0.f) ? E_H : IE_H;
        uint4 v = g_h1s[wid * 8 + l8];
        half2* hp = (half2*)&v;
#pragma unroll
        for (int q = 0; q < 4; q++) {
            float2 f = __half22float2(hp[q]);
            acc[2 * q]     += cf * f.x;
            acc[2 * q + 1] += cf * f.y;
        }
    }
#pragma unroll
    for (int j = 0; j < 8; j++) {
        acc[j] += __shfl_xor_sync(0xffffffffu, acc[j], 8);
        acc[j] += __shfl_xor_sync(0xffffffffu, acc[j], 16);
    }
    if (g == 0) {
#pragma unroll
        for (int j = 0; j < 8; j++)
            so[w][l8 * 8 + j] = fmaxf(acc[j] + b1[l8 * 8 + j], 0.f);
    }
    __syncwarp();
    // fused h2 = o @ W2^T (16 outputs, k split by half-warp)
    float acc2 = 0.f;
    int c = lane & 15;
    int k0 = (lane >> 4) * 32;
#pragma unroll
    for (int k = 0; k < 32; k++) acc2 += so[w][k0 + k] * Wt[(k0 + k) * 16 + c];
    acc2 += __shfl_xor_sync(0xffffffffu, acc2, 16);
    float nb = __shfl_down_sync(0xffffffffu, acc2, 1);
    if (lane < 16 && !(lane & 1)) {
        half2 hh = __floats2half2_rn(acc2, nb);
        g_h2b[wid * 8 + (lane >> 1)] = *(unsigned int*)&hh;
    }
}

// ---------------- E1 layer2: signs + pos counts ----------------
__global__ void k_e1_16() {
    int wid = (blockIdx.x * blockDim.x + threadIdx.x) >> 5;
    if (wid >= NN) return;
    int lane = threadIdx.x & 31;
    int g = lane >> 2, l4 = lane & 3;
    const uint2* h2bv = (const uint2*)g_h2b;
    uint2 dvv = h2bv[wid * 4 + l4];
    half2 d0 = *(half2*)&dvv.x, d1 = *(half2*)&dvv.y;
    float nq = dot4c(d0, d1, dvv);
    nq += __shfl_xor_sync(0xffffffffu, nq, 1);
    nq += __shfl_xor_sync(0xffffffffu, nq, 2);
    if (lane == 0) g_normsq[wid] = nq;
    int beg = g_rowbeg[wid], cnt = g_indeg[wid];
    int i = g;
    for (; i + 8 < cnt; i += 16) {
        int idx0 = beg + i, idx1 = beg + i + 8;
        int s0 = g_srt[idx0];
        int s1 = g_srt[idx1];
        uint2 sv0 = h2bv[s0 * 4 + l4];
        uint2 sv1 = h2bv[s1 * 4 + l4];
        float a0 = dot4c(d0, d1, sv0);
        float a1 = dot4c(d0, d1, sv1);
        a0 += __shfl_xor_sync(0xffffffffu, a0, 1);
        a1 += __shfl_xor_sync(0xffffffffu, a1, 1);
        a0 += __shfl_xor_sync(0xffffffffu, a0, 2);
        a1 += __shfl_xor_sync(0xffffffffu, a1, 2);
        if (l4 == 0) {
            bool sg0 = a0 > 0.f, sg1 = a1 > 0.f;
            g_sign[idx0] = (unsigned char)sg0;
            g_sign[idx1] = (unsigned char)sg1;
            if (sg0) atomicAdd(&g_cntpos[s0], 1);
            if (sg1) atomicAdd(&g_cntpos[s1], 1);
        }
    }
    if (i < cnt) {
        int idx = beg + i;
        int s = g_srt[idx];
        uint2 sv = h2bv[s * 4 + l4];
        float a = dot4c(d0, d1, sv);
        a += __shfl_xor_sync(0xffffffffu, a, 1);
        a += __shfl_xor_sync(0xffffffffu, a, 2);
        if (l4 == 0) {
            bool sg = a > 0.f;
            g_sign[idx] = (unsigned char)sg;
            if (sg) atomicAdd(&g_cntpos[s], 1);
        }
    }
}

// ---------------- W2: scale h2 rows by 1/D; resets cntpos + outdeg ----------------
__global__ void k_w2() {
    int gid = blockIdx.x * blockDim.x + threadIdx.x;
    if (gid >= NN * 4) return;
    int n = gid >> 2, q = gid & 3;
    bool sp = g_normsq[n] > 0.f;
    int p = g_cntpos[n] + (sp ? 1 : 0);
    int tot = g_outdeg[n] + 1;
    float denom = (float)p * E_H + (float)(tot - p) * IE_H;
    float r = __frcp_rn(denom);
    uint2 h = ((const uint2*)g_h2b)[n * 4 + q];
    uint2 o;
    float2 f0 = __half22float2(*(half2*)&h.x);
    float2 f1 = __half22float2(*(half2*)&h.y);
    *(half2*)&o.x = __floats2half2_rn(r * f0.x, r * f0.y);
    *(half2*)&o.y = __floats2half2_rn(r * f1.x, r * f1.y);
    ((uint2*)g_h2s)[n * 4 + q] = o;
    if (q == 0) { g_cntpos[n] = 0; g_outdeg[n] = 0; }
}

// ---------------- E2 layer2: aggregate scaled rows + bias + log_softmax; resets indeg ----------------
__global__ void k_e2_16(const float* __restrict__ b2, float* __restrict__ out) {
    int wid = (blockIdx.x * blockDim.x + threadIdx.x) >> 5;
    if (wid >= NN) return;
    int lane = threadIdx.x & 31;
    int g = lane >> 2, l4 = lane & 3;
    int beg = g_rowbeg[wid], cnt = g_indeg[wid];
    const uint2* h2sv = (const uint2*)g_h2s;
    float4 acc = {0.f, 0.f, 0.f, 0.f};
    int i = g;
    for (; i + 8 < cnt; i += 16) {
        int idx0 = beg + i, idx1 = beg + i + 8;
        int s0 = g_srt[idx0];
        int s1 = g_srt[idx1];
        float w0 = g_sign[idx0] ? E_H : IE_H;
        float w1 = g_sign[idx1] ? E_H : IE_H;
        uint2 v0 = h2sv[s0 * 4 + l4];
        uint2 v1 = h2sv[s1 * 4 + l4];
        float2 p0 = __half22float2(*(half2*)&v0.x);
        float2 p1 = __half22float2(*(half2*)&v0.y);
        float2 q0 = __half22float2(*(half2*)&v1.x);
        float2 q1 = __half22float2(*(half2*)&v1.y);
        acc.x += w0 * p0.x + w1 * q0.x;
        acc.y += w0 * p0.y + w1 * q0.y;
        acc.z += w0 * p1.x + w1 * q1.x;
        acc.w += w0 * p1.y + w1 * q1.y;
    }
    if (i < cnt) {
        int idx = beg + i;
        int s = g_srt[idx];
        float w = g_sign[idx] ? E_H : IE_H;
        uint2 v = h2sv[s * 4 + l4];
        float2 f0 = __half22float2(*(half2*)&v.x);
        float2 f1 = __half22float2(*(half2*)&v.y);
        acc.x += w * f0.x; acc.y += w * f0.y;
        acc.z += w * f1.x; acc.w += w * f1.y;
    }
    if (g == 0) {  // self
        float w = (g_normsq[wid] > 0.f) ? E_H : IE_H;
        uint2 v = h2sv[wid * 4 + l4];
        float2 f0 = __half22float2(*(half2*)&v.x);
        float2 f1 = __half22float2(*(half2*)&v.y);
        acc.x += w * f0.x; acc.y += w * f0.y;
        acc.z += w * f1.x; acc.w += w * f1.y;
    }
#pragma unroll
    for (int o = 4; o < 32; o <<= 1) {
        acc.x += __shfl_xor_sync(0xffffffffu, acc.x, o);
        acc.y += __shfl_xor_sync(0xffffffffu, acc.y, o);
        acc.z += __shfl_xor_sync(0xffffffffu, acc.z, o);
        acc.w += __shfl_xor_sync(0xffffffffu, acc.w, o);
    }
    float4 bb = ((const float4*)b2)[l4];
    float4 v;
    v.x = acc.x + bb.x;
    v.y = acc.y + bb.y;
    v.z = acc.z + bb.z;
    v.w = acc.w + bb.w;
    float m = fmaxf(fmaxf(v.x, v.y), fmaxf(v.z, v.w));
    m = fmaxf(m, __shfl_xor_sync(0xffffffffu, m, 1));
    m = fmaxf(m, __shfl_xor_sync(0xffffffffu, m, 2));
    float e = expf(v.x - m) + expf(v.y - m) + expf(v.z - m) + expf(v.w - m);
    e += __shfl_xor_sync(0xffffffffu, e, 1);
    e += __shfl_xor_sync(0xffffffffu, e, 2);
    float ls = m + logf(e);
    if (lane < 4) {
        float4 rr;
        rr.x = v.x - ls; rr.y = v.y - ls; rr.z = v.z - ls; rr.w = v.w - ls;
        *(float4*)&out[wid * 16 + l4 * 4] = rr;
    }
    if (lane == 0) g_indeg[wid] = 0;  // reset for next call
}

// ---------------- launch ----------------
extern "C" void kernel_launch(void* const* d_in, const int* in_sizes, int n_in,
                              void* d_out, int out_size) {
    (void)in_sizes; (void)n_in; (void)out_size;
    const float* x  = (const float*)d_in[0];
    const int*   ei = (const int*)d_in[1];
    const float* W1 = (const float*)d_in[2];
    const float* b1 = (const float*)d_in[3];
    const float* W2 = (const float*)d_in[4];
    const float* b2 = (const float*)d_in[5];
    float* out = (float*)d_out;

    k_prep<<<SCAT_BLOCKS, 256>>>(ei);
    k_alloc<<<(NN + 255) / 256, 256>>>();
    k_gs<<<GEMM_BLOCKS + SCAT_BLOCKS, 256>>>(x, W1, ei);
    k_e1_64<<<(NN + 7) / 8, 256>>>();          // 4th launch -> profiled
    k_w1<<<(NN * 8 + 255) / 256, 256>>>();
    k_e2_64<<<(NN + 7) / 8, 256>>>(b1, W2);
    k_e1_16<<<(NN + 7) / 8, 256>>>();
    k_w2<<<(NN * 4 + 255) / 256, 256>>>();
    k_e2_16<<<(NN + 7) / 8, 256>>>(b2, out);
}